// round 12
// baseline (speedup 1.0000x reference)
#include <cuda_runtime.h>
#include <cuda_fp16.h>
#include <cstdint>

#define PN 100000
#define LLEN 5
#define NLK 10000
#define DD 32
#define TT 8
#define RUN 256

// Scratch (no allocations allowed)
__device__ float g_path_state[PN * DD];        // 12.8 MB
__device__ float g_link_state[NLK * DD];       // 1.28 MB
__device__ float g_lg[NLK * 3 * DD];           // 3.84 MB
__device__ float g_m[NLK * DD];                // 1.28 MB
__device__ __half g_h1[PN * RUN];              // 51.2 MB : readout hidden 1 (fp16)

__device__ __forceinline__ float fexp2(float x) {
    float r; asm("ex2.approx.f32 %0, %1;" : "=f"(r) : "f"(x)); return r;
}
__device__ __forceinline__ float frcp(float x) {
    float r; asm("rcp.approx.f32 %0, %1;" : "=f"(r) : "f"(x)); return r;
}
__device__ __forceinline__ float fsig(float x) {
    return frcp(1.0f + fexp2(-1.4426950408889634f * x));
}
__device__ __forceinline__ float ftanhf_(float x) {
    float e = fexp2(-2.8853900817779268f * x);
    return fmaf(2.0f, frcp(1.0f + e), -1.0f);
}
__device__ __forceinline__ float fselu(float x) {
    const float sc = 1.0507009873554805f;
    const float sa = 1.7580993408473768f;
    float neg = sa * (fexp2(1.4426950408889634f * x) - 1.0f);
    return x > 0.0f ? sc * x : neg;
}
__device__ __forceinline__ unsigned cvt_tf32(float f) {
    unsigned u; asm("cvt.rna.tf32.f32 %0, %1;" : "=r"(u) : "f"(f)); return u;
}
__device__ __forceinline__ void mma_tf32(float d[4], const unsigned a[4], const unsigned b0,
                                         const unsigned b1) {
    asm volatile(
        "mma.sync.aligned.m16n8k8.row.col.f32.tf32.tf32.f32 "
        "{%0,%1,%2,%3},{%4,%5,%6,%7},{%8,%9},{%0,%1,%2,%3};"
        : "+f"(d[0]), "+f"(d[1]), "+f"(d[2]), "+f"(d[3])
        : "r"(a[0]), "r"(a[1]), "r"(a[2]), "r"(a[3]), "r"(b0), "r"(b1));
}
__device__ __forceinline__ void tf32_split(float v, unsigned& hi, unsigned& lo) {
    hi = cvt_tf32(v);
    lo = cvt_tf32(v - __uint_as_float(hi));
}
__device__ __forceinline__ void mma3(float d[4], const unsigned ah[4], const unsigned al[4],
                                     uint4 b) {
    mma_tf32(d, ah, b.x, b.y);
    mma_tf32(d, al, b.x, b.y);
    mma_tf32(d, ah, b.z, b.w);
}
// 2x compensation: d += (ah + al) * bh  == full-precision A times tf32 B.
__device__ __forceinline__ void mma2(float d[4], const unsigned ah[4], const unsigned al[4],
                                     uint4 b) {
    mma_tf32(d, ah, b.x, b.y);
    mma_tf32(d, al, b.x, b.y);
}

// ---------------------------------------------------------------------------
// Merged init (one launch: path-state init + link-state/lg/m init).
// Also shifts the ncu -s 5 capture window onto path_mma_kernel.
__global__ void init_all_kernel(const float* __restrict__ bw, const float* __restrict__ tos,
                                const float* __restrict__ pk, const float* __restrict__ avg,
                                const float* __restrict__ cap, const float* __restrict__ pol,
                                const float* __restrict__ wt,
                                const float* __restrict__ Wp, const float* __restrict__ bp) {
    int i = blockIdx.x * blockDim.x + threadIdx.x;
    if (i < PN * DD) {
        int p = i >> 5, c = i & 31;
        float v = 0.0f;
        if (c == 0) v = bw[p];
        else if (c == 1) v = tos[p];
        else if (c == 2) v = pk[p];
        else if (c == 3) v = avg[p];
        g_path_state[i] = v;
    }
    int w = i >> 5;
    int lane = i & 31;
    if (w < NLK) {
        float c0 = __ldg(&cap[w]), c1 = __ldg(&pol[w]), c2 = __ldg(&wt[w]);
        float v = (lane == 0) ? c0 : (lane == 1) ? c1 : (lane == 2) ? c2 : 0.0f;
        g_link_state[w * DD + lane] = v;
        g_m[w * DD + lane] = 0.0f;
#pragma unroll
        for (int g = 0; g < 3; g++) {
            int c = g * 32 + lane;
            float o = __ldg(&bp[c]);
            o = fmaf(c0, __ldg(&Wp[c]),       o);
            o = fmaf(c1, __ldg(&Wp[96 + c]),  o);
            o = fmaf(c2, __ldg(&Wp[192 + c]), o);
            g_lg[w * 96 + c] = o;
        }
    }
}

// ---------------------------------------------------------------------------
// Path phase via tensor cores (R11-proven structure). Elementwise GRU now
// batches the z/r reciprocals: one rcp(A*B) replaces two rcp (MUFU is the
// suspected binding pipe; the extra muls ride the idle fma pipe).
__global__ void __launch_bounds__(128)
path_mma_kernel(const int* __restrict__ links, const float* __restrict__ Up,
                const float* __restrict__ bp, int do_scatter) {
    __shared__ uint4 sB[48 * 32];   // [(nt*4+kt)*32 + lane] = {hi0, hi1, lo0, lo1}

    int lane = threadIdx.x & 31;

    for (int idx = threadIdx.x; idx < 48 * 32; idx += blockDim.x) {
        int li = idx & 31;
        int t = idx >> 5;
        int nt = t >> 2, kt = t & 3;
        int gi = li >> 2, mi = li & 3;
        unsigned h0, l0, h1, l1;
        tf32_split(__ldg(&Up[(kt * 8 + mi)     * 96 + nt * 8 + gi]), h0, l0);
        tf32_split(__ldg(&Up[(kt * 8 + mi + 4) * 96 + nt * 8 + gi]), h1, l1);
        sB[idx] = make_uint4(h0, h1, l0, l1);
    }
    __syncthreads();

    int wid = (blockIdx.x * blockDim.x + threadIdx.x) >> 5;
    int p0 = wid * 16;
    if (p0 >= PN) return;
    int g = lane >> 2, m = lane & 3;
    int pA = p0 + g, pB = p0 + g + 8;

    float h[4][4];
#pragma unroll
    for (int jt = 0; jt < 4; jt++) {
        float2 ha = *(const float2*)&g_path_state[pA * DD + 8 * jt + 2 * m];
        float2 hb = *(const float2*)&g_path_state[pB * DD + 8 * jt + 2 * m];
        h[jt][0] = ha.x; h[jt][1] = ha.y; h[jt][2] = hb.x; h[jt][3] = hb.y;
    }

    int lkA[LLEN], lkB[LLEN];
#pragma unroll
    for (int s = 0; s < LLEN; s++) {
        lkA[s] = __ldg(&links[pA * LLEN + s]);
        lkB[s] = __ldg(&links[pB * LLEN + s]);
    }

    float2 br[12];
#pragma unroll
    for (int nt = 0; nt < 12; nt++) {
        int gate = nt >> 2, jt = nt & 3;
        br[nt] = *(const float2*)&bp[96 + gate * 32 + 8 * jt + 2 * m];
    }

    int src0 = (lane & ~3) | (m >> 1);
    int src1 = src0 + 2;
    bool odd = (m & 1);

#pragma unroll 1
    for (int s = 0; s < LLEN; s++) {
        const float* lgA = g_lg + (size_t)lkA[s] * 96;
        const float* lgB = g_lg + (size_t)lkB[s] * 96;

        float2 xg[2][3][4];   // [path][gate][jt]
#pragma unroll
        for (int gate = 0; gate < 3; gate++)
#pragma unroll
            for (int jt = 0; jt < 4; jt++) {
                xg[0][gate][jt] = *(const float2*)&lgA[gate * 32 + 8 * jt + 2 * m];
                xg[1][gate][jt] = *(const float2*)&lgB[gate * 32 + 8 * jt + 2 * m];
            }

        float d[12][4];
#pragma unroll
        for (int nt = 0; nt < 12; nt++) {
            d[nt][0] = br[nt].x; d[nt][1] = br[nt].y;
            d[nt][2] = br[nt].x; d[nt][3] = br[nt].y;
        }

#pragma unroll
        for (int kt = 0; kt < 4; kt++) {
            float v[4];
            float s00 = __shfl_sync(0xffffffffu, h[kt][0], src0);
            float s01 = __shfl_sync(0xffffffffu, h[kt][1], src0);
            v[0] = odd ? s01 : s00;
            float s10 = __shfl_sync(0xffffffffu, h[kt][2], src0);
            float s11 = __shfl_sync(0xffffffffu, h[kt][3], src0);
            v[1] = odd ? s11 : s10;
            float s20 = __shfl_sync(0xffffffffu, h[kt][0], src1);
            float s21 = __shfl_sync(0xffffffffu, h[kt][1], src1);
            v[2] = odd ? s21 : s20;
            float s30 = __shfl_sync(0xffffffffu, h[kt][2], src1);
            float s31 = __shfl_sync(0xffffffffu, h[kt][3], src1);
            v[3] = odd ? s31 : s30;
            unsigned ah[4], al[4];
#pragma unroll
            for (int e = 0; e < 4; e++) tf32_split(v[e], ah[e], al[e]);
#pragma unroll
            for (int nt = 0; nt < 8; nt++)
                mma2(d[nt], ah, al, sB[(nt * 4 + kt) * 32 + lane]);
#pragma unroll
            for (int nt = 8; nt < 12; nt++)
                mma3(d[nt], ah, al, sB[(nt * 4 + kt) * 32 + lane]);
        }

#pragma unroll
        for (int jt = 0; jt < 4; jt++) {
            float xz[4] = {xg[0][0][jt].x, xg[0][0][jt].y, xg[1][0][jt].x, xg[1][0][jt].y};
            float xr[4] = {xg[0][1][jt].x, xg[0][1][jt].y, xg[1][1][jt].x, xg[1][1][jt].y};
            float xn[4] = {xg[0][2][jt].x, xg[0][2][jt].y, xg[1][2][jt].x, xg[1][2][jt].y};
#pragma unroll
            for (int e = 0; e < 4; e++) {
                // Batched reciprocal: z = 1/A, r = 1/B via one rcp(A*B).
                float A = 1.0f + fexp2(-1.4426950408889634f * (d[jt][e] + xz[e]));
                float B = 1.0f + fexp2(-1.4426950408889634f * (d[4 + jt][e] + xr[e]));
                float ip = frcp(A * B);
                float z = B * ip;
                float r = A * ip;
                float n = ftanhf_(fmaf(r, d[8 + jt][e], xn[e]));
                h[jt][e] = fmaf(z, h[jt][e] - n, n);
            }
            if (do_scatter) {
                int cA = 8 * jt + 2 * m;
                atomicAdd((float2*)&g_m[lkA[s] * DD + cA], make_float2(h[jt][0], h[jt][1]));
                atomicAdd((float2*)&g_m[lkB[s] * DD + cA], make_float2(h[jt][2], h[jt][3]));
            }
        }
    }

#pragma unroll
    for (int jt = 0; jt < 4; jt++) {
        *(float2*)&g_path_state[pA * DD + 8 * jt + 2 * m] = make_float2(h[jt][0], h[jt][1]);
        *(float2*)&g_path_state[pB * DD + 8 * jt + 2 * m] = make_float2(h[jt][2], h[jt][3]);
    }
}

// ---------------------------------------------------------------------------
// Link phase via tensor cores (3xTF32), R6-proven. Warp = 16 links.
__global__ void __launch_bounds__(128)
link_mma_kernel(const float* __restrict__ Wl, const float* __restrict__ Ul,
                const float* __restrict__ bl,
                const float* __restrict__ Wp, const float* __restrict__ bp) {
    __shared__ float2 sWl[48 * 32], sUl[48 * 32], sWp[48 * 32];   // 36KB

    int lane = threadIdx.x & 31;
    for (int idx = threadIdx.x; idx < 48 * 32; idx += blockDim.x) {
        int li = idx & 31;
        int t = idx >> 5;
        int nt = t >> 2, kt = t & 3;
        int gi = li >> 2, mi = li & 3;
        int r0 = (kt * 8 + mi) * 96 + nt * 8 + gi;
        int r1 = (kt * 8 + mi + 4) * 96 + nt * 8 + gi;
        sWl[idx] = make_float2(__ldg(&Wl[r0]), __ldg(&Wl[r1]));
        sUl[idx] = make_float2(__ldg(&Ul[r0]), __ldg(&Ul[r1]));
        sWp[idx] = make_float2(__ldg(&Wp[r0]), __ldg(&Wp[r1]));
    }
    __syncthreads();

    int wid = (blockIdx.x * blockDim.x + threadIdx.x) >> 5;
    int l0 = wid * 16;
    if (l0 >= NLK) return;
    int g = lane >> 2, m = lane & 3;
    int lA = l0 + g, lB = l0 + g + 8;

    unsigned xh[4][4], xlo[4][4], hh[4][4], hlo[4][4];
#pragma unroll
    for (int kt = 0; kt < 4; kt++) {
        tf32_split(g_m[lA * DD + kt * 8 + m],     xh[kt][0], xlo[kt][0]);
        tf32_split(g_m[lB * DD + kt * 8 + m],     xh[kt][1], xlo[kt][1]);
        tf32_split(g_m[lA * DD + kt * 8 + m + 4], xh[kt][2], xlo[kt][2]);
        tf32_split(g_m[lB * DD + kt * 8 + m + 4], xh[kt][3], xlo[kt][3]);
        tf32_split(g_link_state[lA * DD + kt * 8 + m],     hh[kt][0], hlo[kt][0]);
        tf32_split(g_link_state[lB * DD + kt * 8 + m],     hh[kt][1], hlo[kt][1]);
        tf32_split(g_link_state[lA * DD + kt * 8 + m + 4], hh[kt][2], hlo[kt][2]);
        tf32_split(g_link_state[lB * DD + kt * 8 + m + 4], hh[kt][3], hlo[kt][3]);
    }

    float dz[4][4], dr[4][4], dxn[4][4], dhn[4][4];
#pragma unroll
    for (int jt = 0; jt < 4; jt++) {
        int col = 8 * jt + 2 * m;
        float2 b0z = *(const float2*)&bl[col];
        float2 b1z = *(const float2*)&bl[96 + col];
        dz[jt][0] = b0z.x + b1z.x; dz[jt][1] = b0z.y + b1z.y;
        dz[jt][2] = dz[jt][0];     dz[jt][3] = dz[jt][1];
        float2 b0r = *(const float2*)&bl[32 + col];
        float2 b1r = *(const float2*)&bl[128 + col];
        dr[jt][0] = b0r.x + b1r.x; dr[jt][1] = b0r.y + b1r.y;
        dr[jt][2] = dr[jt][0];     dr[jt][3] = dr[jt][1];
        float2 b0n = *(const float2*)&bl[64 + col];
        dxn[jt][0] = b0n.x; dxn[jt][1] = b0n.y; dxn[jt][2] = b0n.x; dxn[jt][3] = b0n.y;
        float2 b1n = *(const float2*)&bl[160 + col];
        dhn[jt][0] = b1n.x; dhn[jt][1] = b1n.y; dhn[jt][2] = b1n.x; dhn[jt][3] = b1n.y;
    }

#pragma unroll
    for (int jt = 0; jt < 4; jt++)
#pragma unroll
        for (int kt = 0; kt < 4; kt++) {
            float2 bw; unsigned bh0, bl0, bh1, bl1;
            bw = sWl[(jt * 4 + kt) * 32 + lane];
            tf32_split(bw.x, bh0, bl0); tf32_split(bw.y, bh1, bl1);
            mma_tf32(dz[jt], xh[kt], bh0, bh1);
            mma_tf32(dz[jt], xlo[kt], bh0, bh1);
            mma_tf32(dz[jt], xh[kt], bl0, bl1);
            bw = sUl[(jt * 4 + kt) * 32 + lane];
            tf32_split(bw.x, bh0, bl0); tf32_split(bw.y, bh1, bl1);
            mma_tf32(dz[jt], hh[kt], bh0, bh1);
            mma_tf32(dz[jt], hlo[kt], bh0, bh1);
            mma_tf32(dz[jt], hh[kt], bl0, bl1);
            bw = sWl[((4 + jt) * 4 + kt) * 32 + lane];
            tf32_split(bw.x, bh0, bl0); tf32_split(bw.y, bh1, bl1);
            mma_tf32(dr[jt], xh[kt], bh0, bh1);
            mma_tf32(dr[jt], xlo[kt], bh0, bh1);
            mma_tf32(dr[jt], xh[kt], bl0, bl1);
            bw = sUl[((4 + jt) * 4 + kt) * 32 + lane];
            tf32_split(bw.x, bh0, bl0); tf32_split(bw.y, bh1, bl1);
            mma_tf32(dr[jt], hh[kt], bh0, bh1);
            mma_tf32(dr[jt], hlo[kt], bh0, bh1);
            mma_tf32(dr[jt], hh[kt], bl0, bl1);
            bw = sWl[((8 + jt) * 4 + kt) * 32 + lane];
            tf32_split(bw.x, bh0, bl0); tf32_split(bw.y, bh1, bl1);
            mma_tf32(dxn[jt], xh[kt], bh0, bh1);
            mma_tf32(dxn[jt], xlo[kt], bh0, bh1);
            mma_tf32(dxn[jt], xh[kt], bl0, bl1);
            bw = sUl[((8 + jt) * 4 + kt) * 32 + lane];
            tf32_split(bw.x, bh0, bl0); tf32_split(bw.y, bh1, bl1);
            mma_tf32(dhn[jt], hh[kt], bh0, bh1);
            mma_tf32(dhn[jt], hlo[kt], bh0, bh1);
            mma_tf32(dhn[jt], hh[kt], bl0, bl1);
        }

    float h2[4][4];
#pragma unroll
    for (int jt = 0; jt < 4; jt++) {
        int col = 8 * jt + 2 * m;
        float2 hA = *(const float2*)&g_link_state[lA * DD + col];
        float2 hB = *(const float2*)&g_link_state[lB * DD + col];
        float hd[4] = {hA.x, hA.y, hB.x, hB.y};
#pragma unroll
        for (int e = 0; e < 4; e++) {
            float z = fsig(dz[jt][e]);
            float r = fsig(dr[jt][e]);
            float n = ftanhf_(fmaf(r, dhn[jt][e], dxn[jt][e]));
            h2[jt][e] = fmaf(z, hd[e] - n, n);
        }
        *(float2*)&g_link_state[lA * DD + col] = make_float2(h2[jt][0], h2[jt][1]);
        *(float2*)&g_link_state[lB * DD + col] = make_float2(h2[jt][2], h2[jt][3]);
        *(float2*)&g_m[lA * DD + col] = make_float2(0.0f, 0.0f);
        *(float2*)&g_m[lB * DD + col] = make_float2(0.0f, 0.0f);
    }

    int src0 = (lane & ~3) | (m >> 1);
    int src1 = src0 + 2;
    bool odd = (m & 1);
    unsigned ah[4][4], al[4][4];
#pragma unroll
    for (int kt = 0; kt < 4; kt++) {
        float v[4];
        float s00 = __shfl_sync(0xffffffffu, h2[kt][0], src0);
        float s01 = __shfl_sync(0xffffffffu, h2[kt][1], src0);
        v[0] = odd ? s01 : s00;
        float s10 = __shfl_sync(0xffffffffu, h2[kt][2], src0);
        float s11 = __shfl_sync(0xffffffffu, h2[kt][3], src0);
        v[1] = odd ? s11 : s10;
        float s20 = __shfl_sync(0xffffffffu, h2[kt][0], src1);
        float s21 = __shfl_sync(0xffffffffu, h2[kt][1], src1);
        v[2] = odd ? s21 : s20;
        float s30 = __shfl_sync(0xffffffffu, h2[kt][2], src1);
        float s31 = __shfl_sync(0xffffffffu, h2[kt][3], src1);
        v[3] = odd ? s31 : s30;
#pragma unroll
        for (int e = 0; e < 4; e++) tf32_split(v[e], ah[kt][e], al[kt][e]);
    }
#pragma unroll
    for (int nt = 0; nt < 12; nt++) {
        float d2[4];
        int col = nt * 8 + 2 * m;
        float2 b = *(const float2*)&bp[col];
        d2[0] = b.x; d2[1] = b.y; d2[2] = b.x; d2[3] = b.y;
#pragma unroll
        for (int kt = 0; kt < 4; kt++) {
            float2 bw = sWp[(nt * 4 + kt) * 32 + lane];
            unsigned bh0, bl0, bh1, bl1;
            tf32_split(bw.x, bh0, bl0); tf32_split(bw.y, bh1, bl1);
            mma_tf32(d2, ah[kt], bh0, bh1);
            mma_tf32(d2, al[kt], bh0, bh1);
            mma_tf32(d2, ah[kt], bl0, bl1);
        }
        *(float2*)&g_lg[lA * 96 + col] = make_float2(d2[0], d2[1]);
        *(float2*)&g_lg[lB * 96 + col] = make_float2(d2[2], d2[3]);
    }
}

// ---------------------------------------------------------------------------
// Readout layer 1: H1 = selu(PS @ R1 + b1), stored fp16.
__global__ void __launch_bounds__(256)
readout1_kernel(const float* __restrict__ R1, const float* __restrict__ Rb1) {
    __shared__ float2 sB[32 * 4 * 32];

    int lane = threadIdx.x & 31;
    for (int idx = threadIdx.x; idx < 32 * 4 * 32; idx += blockDim.x) {
        int li = idx & 31;
        int t = idx >> 5;
        int nt = t >> 2, kt = t & 3;
        int gi = li >> 2, mi = li & 3;
        sB[idx] = make_float2(__ldg(&R1[(kt * 8 + mi)     * RUN + nt * 8 + gi]),
                              __ldg(&R1[(kt * 8 + mi + 4) * RUN + nt * 8 + gi]));
    }
    __syncthreads();

    int wid = (blockIdx.x * blockDim.x + threadIdx.x) >> 5;
    int p0 = wid * 16;
    if (p0 >= PN) return;
    int g = lane >> 2, m = lane & 3;
    int pA = p0 + g, pB = p0 + g + 8;

    unsigned ah[4][4], al[4][4];
#pragma unroll
    for (int kt = 0; kt < 4; kt++) {
        tf32_split(__ldg(&g_path_state[pA * DD + kt * 8 + m]),     ah[kt][0], al[kt][0]);
        tf32_split(__ldg(&g_path_state[pB * DD + kt * 8 + m]),     ah[kt][1], al[kt][1]);
        tf32_split(__ldg(&g_path_state[pA * DD + kt * 8 + m + 4]), ah[kt][2], al[kt][2]);
        tf32_split(__ldg(&g_path_state[pB * DD + kt * 8 + m + 4]), ah[kt][3], al[kt][3]);
    }

#pragma unroll 1
    for (int half = 0; half < 2; half++) {
        float d[16][4];
#pragma unroll
        for (int ntl = 0; ntl < 16; ntl++) {
            int col = (half * 16 + ntl) * 8 + 2 * m;
            float2 b = *(const float2*)&Rb1[col];
            d[ntl][0] = b.x; d[ntl][1] = b.y; d[ntl][2] = b.x; d[ntl][3] = b.y;
        }
#pragma unroll
        for (int ntl = 0; ntl < 16; ntl++) {
            int nt = half * 16 + ntl;
#pragma unroll
            for (int kt = 0; kt < 4; kt++) {
                float2 b = sB[(nt * 4 + kt) * 32 + lane];
                unsigned bh0, bl0, bh1, bl1;
                tf32_split(b.x, bh0, bl0);
                tf32_split(b.y, bh1, bl1);
                mma_tf32(d[ntl], ah[kt], bh0, bh1);
                mma_tf32(d[ntl], al[kt], bh0, bh1);
                mma_tf32(d[ntl], ah[kt], bl0, bl1);
            }
        }
#pragma unroll
        for (int ntl = 0; ntl < 16; ntl++) {
            int col = (half * 16 + ntl) * 8 + 2 * m;
            *(__half2*)&g_h1[pA * RUN + col] =
                __floats2half2_rn(fselu(d[ntl][0]), fselu(d[ntl][1]));
            *(__half2*)&g_h1[pB * RUN + col] =
                __floats2half2_rn(fselu(d[ntl][2]), fselu(d[ntl][3]));
        }
    }
}

// ---------------------------------------------------------------------------
// Readout layers 2+3: out = selu(H1 @ R2 + b2) @ R3 + b3. A fp16-exact in tf32.
__global__ void __launch_bounds__(256)
readout2_kernel(const float* __restrict__ R2, const float* __restrict__ Rb2,
                const float* __restrict__ R3, const float* __restrict__ Rb3,
                float* __restrict__ out) {
    __shared__ float2 sB[16 * 8 * 32];

    int lane = threadIdx.x & 31;
    int wid = (blockIdx.x * blockDim.x + threadIdx.x) >> 5;
    int p0 = wid * 16;
    bool active = (p0 < PN);
    int g = lane >> 2, m = lane & 3;
    int pA = p0 + g, pB = p0 + g + 8;

    float accA = 0.0f, accB = 0.0f;

#pragma unroll 1
    for (int half = 0; half < 2; half++) {
        float d[16][4];
        if (active) {
#pragma unroll
            for (int ntl = 0; ntl < 16; ntl++) {
                int col = half * 128 + ntl * 8 + 2 * m;
                float2 b = *(const float2*)&Rb2[col];
                d[ntl][0] = b.x; d[ntl][1] = b.y; d[ntl][2] = b.x; d[ntl][3] = b.y;
            }
        }
#pragma unroll 1
        for (int kc = 0; kc < 4; kc++) {
            __syncthreads();
            for (int idx = threadIdx.x; idx < 16 * 8 * 32; idx += blockDim.x) {
                int li = idx & 31;
                int t = idx >> 5;
                int ntl = t >> 3, kt = t & 7;
                int gi = li >> 2, mi = li & 3;
                int krow = kc * 64 + kt * 8;
                int col = half * 128 + ntl * 8 + gi;
                sB[idx] = make_float2(__ldg(&R2[(krow + mi)     * RUN + col]),
                                      __ldg(&R2[(krow + mi + 4) * RUN + col]));
            }
            __syncthreads();
            if (!active) continue;

            unsigned a[8][4];
#pragma unroll
            for (int kt = 0; kt < 8; kt++) {
                int k0 = kc * 64 + kt * 8;
                a[kt][0] = cvt_tf32(__half2float(g_h1[pA * RUN + k0 + m]));
                a[kt][1] = cvt_tf32(__half2float(g_h1[pB * RUN + k0 + m]));
                a[kt][2] = cvt_tf32(__half2float(g_h1[pA * RUN + k0 + m + 4]));
                a[kt][3] = cvt_tf32(__half2float(g_h1[pB * RUN + k0 + m + 4]));
            }
#pragma unroll
            for (int ntl = 0; ntl < 16; ntl++)
#pragma unroll
                for (int kt = 0; kt < 8; kt++) {
                    float2 b = sB[(ntl * 8 + kt) * 32 + lane];
                    unsigned bh0, bl0, bh1, bl1;
                    tf32_split(b.x, bh0, bl0);
                    tf32_split(b.y, bh1, bl1);
                    mma_tf32(d[ntl], a[kt], bh0, bh1);
                    mma_tf32(d[ntl], a[kt], bl0, bl1);
                }
        }
        if (active) {
#pragma unroll
            for (int ntl = 0; ntl < 16; ntl++) {
                int col = half * 128 + ntl * 8 + 2 * m;
                float2 r3 = *(const float2*)&R3[col];
                accA = fmaf(fselu(d[ntl][0]), r3.x, accA);
                accA = fmaf(fselu(d[ntl][1]), r3.y, accA);
                accB = fmaf(fselu(d[ntl][2]), r3.x, accB);
                accB = fmaf(fselu(d[ntl][3]), r3.y, accB);
            }
        }
    }

    if (active) {
        accA += __shfl_xor_sync(0xffffffffu, accA, 1);
        accA += __shfl_xor_sync(0xffffffffu, accA, 2);
        accB += __shfl_xor_sync(0xffffffffu, accB, 1);
        accB += __shfl_xor_sync(0xffffffffu, accB, 2);
        if (m == 0) {
            float b3 = __ldg(&Rb3[0]);
            out[pA] = accA + b3;
            out[pB] = accB + b3;
        }
    }
}

// ---------------------------------------------------------------------------
extern "C" void kernel_launch(void* const* d_in, const int* in_sizes, int n_in,
                              void* d_out, int out_size) {
    const int*   links = (const int*)d_in[0];
    const float* cap = (const float*)d_in[3];
    const float* pol = (const float*)d_in[4];
    const float* wt  = (const float*)d_in[5];
    const float* bw  = (const float*)d_in[6];
    const float* tos = (const float*)d_in[7];
    const float* pk  = (const float*)d_in[8];
    const float* avg = (const float*)d_in[9];
    const float* Wp  = (const float*)d_in[10];
    const float* Up  = (const float*)d_in[11];
    const float* bp  = (const float*)d_in[12];
    const float* Wl  = (const float*)d_in[13];
    const float* Ul  = (const float*)d_in[14];
    const float* bl  = (const float*)d_in[15];
    const float* R1  = (const float*)d_in[16];
    const float* Rb1 = (const float*)d_in[17];
    const float* R2  = (const float*)d_in[18];
    const float* Rb2 = (const float*)d_in[19];
    const float* R3  = (const float*)d_in[20];
    const float* Rb3 = (const float*)d_in[21];
    float* out = (float*)d_out;

    init_all_kernel<<<(PN * DD + 255) / 256, 256>>>(bw, tos, pk, avg, cap, pol, wt, Wp, bp);

    int nwarps = (PN + 15) / 16;               // 6250
    int pblocks = (nwarps + 3) / 4;            // 128 threads = 4 warps per block
    int lwarps = (NLK + 15) / 16;              // 625
    int lblocks = (lwarps + 3) / 4;            // 157
    for (int t = 0; t < TT; t++) {
        path_mma_kernel<<<pblocks, 128>>>(links, Up, bp, t < TT - 1 ? 1 : 0);
        if (t < TT - 1)
            link_mma_kernel<<<lblocks, 128>>>(Wl, Ul, bl, Wp, bp);
    }

    int rblocks = (nwarps + 7) / 8;            // 256 threads = 8 warps per block
    readout1_kernel<<<rblocks, 256>>>(R1, Rb1);
    readout2_kernel<<<rblocks, 256>>>(R2, Rb2, R3, Rb3, out);
}

// round 13
// speedup vs baseline: 1.0385x; 1.0385x over previous
#include <cuda_runtime.h>
#include <cuda_fp16.h>
#include <cstdint>

#define PN 100000
#define LLEN 5
#define NLK 10000
#define DD 32
#define TT 8
#define RUN 256

// Scratch (no allocations allowed)
__device__ float g_path_state[PN * DD];        // 12.8 MB
__device__ float g_link_state[NLK * DD];       // 1.28 MB
__device__ float g_lg[NLK * 3 * DD];           // 3.84 MB
__device__ float g_m[NLK * DD];                // 1.28 MB
__device__ __half g_h1[PN * RUN];              // 51.2 MB : readout hidden 1 (fp16)

__device__ __forceinline__ float fexp2(float x) {
    float r; asm("ex2.approx.f32 %0, %1;" : "=f"(r) : "f"(x)); return r;
}
__device__ __forceinline__ float frcp(float x) {
    float r; asm("rcp.approx.f32 %0, %1;" : "=f"(r) : "f"(x)); return r;
}
__device__ __forceinline__ float fsig(float x) {
    return frcp(1.0f + fexp2(-1.4426950408889634f * x));
}
__device__ __forceinline__ float ftanhf_(float x) {
    float e = fexp2(-2.8853900817779268f * x);
    return fmaf(2.0f, frcp(1.0f + e), -1.0f);
}
__device__ __forceinline__ float fselu(float x) {
    const float sc = 1.0507009873554805f;
    const float sa = 1.7580993408473768f;
    float neg = sa * (fexp2(1.4426950408889634f * x) - 1.0f);
    return x > 0.0f ? sc * x : neg;
}
__device__ __forceinline__ unsigned cvt_tf32(float f) {
    unsigned u; asm("cvt.rna.tf32.f32 %0, %1;" : "=r"(u) : "f"(f)); return u;
}
__device__ __forceinline__ void mma_tf32(float d[4], const unsigned a[4], const unsigned b0,
                                         const unsigned b1) {
    asm volatile(
        "mma.sync.aligned.m16n8k8.row.col.f32.tf32.tf32.f32 "
        "{%0,%1,%2,%3},{%4,%5,%6,%7},{%8,%9},{%0,%1,%2,%3};"
        : "+f"(d[0]), "+f"(d[1]), "+f"(d[2]), "+f"(d[3])
        : "r"(a[0]), "r"(a[1]), "r"(a[2]), "r"(a[3]), "r"(b0), "r"(b1));
}
__device__ __forceinline__ void tf32_split(float v, unsigned& hi, unsigned& lo) {
    hi = cvt_tf32(v);
    lo = cvt_tf32(v - __uint_as_float(hi));
}
__device__ __forceinline__ void mma3(float d[4], const unsigned ah[4], const unsigned al[4],
                                     uint4 b) {
    mma_tf32(d, ah, b.x, b.y);
    mma_tf32(d, al, b.x, b.y);
    mma_tf32(d, ah, b.z, b.w);
}
// 2x compensation with hi-only fragment: d += (ah + al) * bh.
__device__ __forceinline__ void mma2h(float d[4], const unsigned ah[4], const unsigned al[4],
                                      uint2 b) {
    mma_tf32(d, ah, b.x, b.y);
    mma_tf32(d, al, b.x, b.y);
}

// ---------------------------------------------------------------------------
// Merged init (one launch): path-state init + link-state/lg/m init.
__global__ void init_all_kernel(const float* __restrict__ bw, const float* __restrict__ tos,
                                const float* __restrict__ pk, const float* __restrict__ avg,
                                const float* __restrict__ cap, const float* __restrict__ pol,
                                const float* __restrict__ wt,
                                const float* __restrict__ Wp, const float* __restrict__ bp) {
    int i = blockIdx.x * blockDim.x + threadIdx.x;
    if (i < PN * DD) {
        int p = i >> 5, c = i & 31;
        float v = 0.0f;
        if (c == 0) v = bw[p];
        else if (c == 1) v = tos[p];
        else if (c == 2) v = pk[p];
        else if (c == 3) v = avg[p];
        g_path_state[i] = v;
    }
    int w = i >> 5;
    int lane = i & 31;
    if (w < NLK) {
        float c0 = __ldg(&cap[w]), c1 = __ldg(&pol[w]), c2 = __ldg(&wt[w]);
        float v = (lane == 0) ? c0 : (lane == 1) ? c1 : (lane == 2) ? c2 : 0.0f;
        g_link_state[w * DD + lane] = v;
        g_m[w * DD + lane] = 0.0f;
#pragma unroll
        for (int g = 0; g < 3; g++) {
            int c = g * 32 + lane;
            float o = __ldg(&bp[c]);
            o = fmaf(c0, __ldg(&Wp[c]),       o);
            o = fmaf(c1, __ldg(&Wp[96 + c]),  o);
            o = fmaf(c2, __ldg(&Wp[192 + c]), o);
            g_lg[w * 96 + c] = o;
        }
    }
}

// ---------------------------------------------------------------------------
// Path phase via tensor cores. L1-traffic cut: z/r fragments stored hi-only
// (uint2, mma2 never reads lo), n fragments full uint4. LDS bytes -33%.
// Elementwise GRU reverted to the R11-proven plain fsig form.
__global__ void __launch_bounds__(128)
path_mma_kernel(const int* __restrict__ links, const float* __restrict__ Up,
                const float* __restrict__ bp, int do_scatter) {
    __shared__ uint2 sBzr[32 * 32];   // z/r tiles: [(nt*4+kt)*32 + lane] = {hi0, hi1}
    __shared__ uint4 sBn[16 * 32];    // n tiles: [((nt-8)*4+kt)*32 + lane]

    int lane = threadIdx.x & 31;

    // Stage z/r (hi only)
    for (int idx = threadIdx.x; idx < 32 * 32; idx += blockDim.x) {
        int li = idx & 31;
        int t = idx >> 5;             // nt*4 + kt, nt in [0,8)
        int nt = t >> 2, kt = t & 3;
        int gi = li >> 2, mi = li & 3;
        unsigned h0 = cvt_tf32(__ldg(&Up[(kt * 8 + mi)     * 96 + nt * 8 + gi]));
        unsigned h1 = cvt_tf32(__ldg(&Up[(kt * 8 + mi + 4) * 96 + nt * 8 + gi]));
        sBzr[idx] = make_uint2(h0, h1);
    }
    // Stage n (hi + lo)
    for (int idx = threadIdx.x; idx < 16 * 32; idx += blockDim.x) {
        int li = idx & 31;
        int t = idx >> 5;             // (nt-8)*4 + kt
        int nt = (t >> 2) + 8, kt = t & 3;
        int gi = li >> 2, mi = li & 3;
        unsigned h0, l0, h1, l1;
        tf32_split(__ldg(&Up[(kt * 8 + mi)     * 96 + nt * 8 + gi]), h0, l0);
        tf32_split(__ldg(&Up[(kt * 8 + mi + 4) * 96 + nt * 8 + gi]), h1, l1);
        sBn[idx] = make_uint4(h0, h1, l0, l1);
    }
    __syncthreads();

    int wid = (blockIdx.x * blockDim.x + threadIdx.x) >> 5;
    int p0 = wid * 16;
    if (p0 >= PN) return;
    int g = lane >> 2, m = lane & 3;
    int pA = p0 + g, pB = p0 + g + 8;

    float h[4][4];
#pragma unroll
    for (int jt = 0; jt < 4; jt++) {
        float2 ha = *(const float2*)&g_path_state[pA * DD + 8 * jt + 2 * m];
        float2 hb = *(const float2*)&g_path_state[pB * DD + 8 * jt + 2 * m];
        h[jt][0] = ha.x; h[jt][1] = ha.y; h[jt][2] = hb.x; h[jt][3] = hb.y;
    }

    int lkA[LLEN], lkB[LLEN];
#pragma unroll
    for (int s = 0; s < LLEN; s++) {
        lkA[s] = __ldg(&links[pA * LLEN + s]);
        lkB[s] = __ldg(&links[pB * LLEN + s]);
    }

    float2 br[12];
#pragma unroll
    for (int nt = 0; nt < 12; nt++) {
        int gate = nt >> 2, jt = nt & 3;
        br[nt] = *(const float2*)&bp[96 + gate * 32 + 8 * jt + 2 * m];
    }

    int src0 = (lane & ~3) | (m >> 1);
    int src1 = src0 + 2;
    bool odd = (m & 1);

#pragma unroll 1
    for (int s = 0; s < LLEN; s++) {
        const float* lgA = g_lg + (size_t)lkA[s] * 96;
        const float* lgB = g_lg + (size_t)lkB[s] * 96;

        float2 xg[2][3][4];   // [path][gate][jt]
#pragma unroll
        for (int gate = 0; gate < 3; gate++)
#pragma unroll
            for (int jt = 0; jt < 4; jt++) {
                xg[0][gate][jt] = *(const float2*)&lgA[gate * 32 + 8 * jt + 2 * m];
                xg[1][gate][jt] = *(const float2*)&lgB[gate * 32 + 8 * jt + 2 * m];
            }

        float d[12][4];
#pragma unroll
        for (int nt = 0; nt < 12; nt++) {
            d[nt][0] = br[nt].x; d[nt][1] = br[nt].y;
            d[nt][2] = br[nt].x; d[nt][3] = br[nt].y;
        }

#pragma unroll
        for (int kt = 0; kt < 4; kt++) {
            float v[4];
            float s00 = __shfl_sync(0xffffffffu, h[kt][0], src0);
            float s01 = __shfl_sync(0xffffffffu, h[kt][1], src0);
            v[0] = odd ? s01 : s00;
            float s10 = __shfl_sync(0xffffffffu, h[kt][2], src0);
            float s11 = __shfl_sync(0xffffffffu, h[kt][3], src0);
            v[1] = odd ? s11 : s10;
            float s20 = __shfl_sync(0xffffffffu, h[kt][0], src1);
            float s21 = __shfl_sync(0xffffffffu, h[kt][1], src1);
            v[2] = odd ? s21 : s20;
            float s30 = __shfl_sync(0xffffffffu, h[kt][2], src1);
            float s31 = __shfl_sync(0xffffffffu, h[kt][3], src1);
            v[3] = odd ? s31 : s30;
            unsigned ah[4], al[4];
#pragma unroll
            for (int e = 0; e < 4; e++) tf32_split(v[e], ah[e], al[e]);
#pragma unroll
            for (int nt = 0; nt < 8; nt++)
                mma2h(d[nt], ah, al, sBzr[(nt * 4 + kt) * 32 + lane]);
#pragma unroll
            for (int nt = 8; nt < 12; nt++)
                mma3(d[nt], ah, al, sBn[((nt - 8) * 4 + kt) * 32 + lane]);
        }

#pragma unroll
        for (int jt = 0; jt < 4; jt++) {
            float xz[4] = {xg[0][0][jt].x, xg[0][0][jt].y, xg[1][0][jt].x, xg[1][0][jt].y};
            float xr[4] = {xg[0][1][jt].x, xg[0][1][jt].y, xg[1][1][jt].x, xg[1][1][jt].y};
            float xn[4] = {xg[0][2][jt].x, xg[0][2][jt].y, xg[1][2][jt].x, xg[1][2][jt].y};
#pragma unroll
            for (int e = 0; e < 4; e++) {
                float z = fsig(d[jt][e] + xz[e]);
                float r = fsig(d[4 + jt][e] + xr[e]);
                float n = ftanhf_(fmaf(r, d[8 + jt][e], xn[e]));
                h[jt][e] = fmaf(z, h[jt][e] - n, n);
            }
            if (do_scatter) {
                int cA = 8 * jt + 2 * m;
                atomicAdd((float2*)&g_m[lkA[s] * DD + cA], make_float2(h[jt][0], h[jt][1]));
                atomicAdd((float2*)&g_m[lkB[s] * DD + cA], make_float2(h[jt][2], h[jt][3]));
            }
        }
    }

#pragma unroll
    for (int jt = 0; jt < 4; jt++) {
        *(float2*)&g_path_state[pA * DD + 8 * jt + 2 * m] = make_float2(h[jt][0], h[jt][1]);
        *(float2*)&g_path_state[pB * DD + 8 * jt + 2 * m] = make_float2(h[jt][2], h[jt][3]);
    }
}

// ---------------------------------------------------------------------------
// Link phase via tensor cores (3xTF32), R6-proven. Warp = 16 links.
__global__ void __launch_bounds__(128)
link_mma_kernel(const float* __restrict__ Wl, const float* __restrict__ Ul,
                const float* __restrict__ bl,
                const float* __restrict__ Wp, const float* __restrict__ bp) {
    __shared__ float2 sWl[48 * 32], sUl[48 * 32], sWp[48 * 32];   // 36KB

    int lane = threadIdx.x & 31;
    for (int idx = threadIdx.x; idx < 48 * 32; idx += blockDim.x) {
        int li = idx & 31;
        int t = idx >> 5;
        int nt = t >> 2, kt = t & 3;
        int gi = li >> 2, mi = li & 3;
        int r0 = (kt * 8 + mi) * 96 + nt * 8 + gi;
        int r1 = (kt * 8 + mi + 4) * 96 + nt * 8 + gi;
        sWl[idx] = make_float2(__ldg(&Wl[r0]), __ldg(&Wl[r1]));
        sUl[idx] = make_float2(__ldg(&Ul[r0]), __ldg(&Ul[r1]));
        sWp[idx] = make_float2(__ldg(&Wp[r0]), __ldg(&Wp[r1]));
    }
    __syncthreads();

    int wid = (blockIdx.x * blockDim.x + threadIdx.x) >> 5;
    int l0 = wid * 16;
    if (l0 >= NLK) return;
    int g = lane >> 2, m = lane & 3;
    int lA = l0 + g, lB = l0 + g + 8;

    unsigned xh[4][4], xlo[4][4], hh[4][4], hlo[4][4];
#pragma unroll
    for (int kt = 0; kt < 4; kt++) {
        tf32_split(g_m[lA * DD + kt * 8 + m],     xh[kt][0], xlo[kt][0]);
        tf32_split(g_m[lB * DD + kt * 8 + m],     xh[kt][1], xlo[kt][1]);
        tf32_split(g_m[lA * DD + kt * 8 + m + 4], xh[kt][2], xlo[kt][2]);
        tf32_split(g_m[lB * DD + kt * 8 + m + 4], xh[kt][3], xlo[kt][3]);
        tf32_split(g_link_state[lA * DD + kt * 8 + m],     hh[kt][0], hlo[kt][0]);
        tf32_split(g_link_state[lB * DD + kt * 8 + m],     hh[kt][1], hlo[kt][1]);
        tf32_split(g_link_state[lA * DD + kt * 8 + m + 4], hh[kt][2], hlo[kt][2]);
        tf32_split(g_link_state[lB * DD + kt * 8 + m + 4], hh[kt][3], hlo[kt][3]);
    }

    float dz[4][4], dr[4][4], dxn[4][4], dhn[4][4];
#pragma unroll
    for (int jt = 0; jt < 4; jt++) {
        int col = 8 * jt + 2 * m;
        float2 b0z = *(const float2*)&bl[col];
        float2 b1z = *(const float2*)&bl[96 + col];
        dz[jt][0] = b0z.x + b1z.x; dz[jt][1] = b0z.y + b1z.y;
        dz[jt][2] = dz[jt][0];     dz[jt][3] = dz[jt][1];
        float2 b0r = *(const float2*)&bl[32 + col];
        float2 b1r = *(const float2*)&bl[128 + col];
        dr[jt][0] = b0r.x + b1r.x; dr[jt][1] = b0r.y + b1r.y;
        dr[jt][2] = dr[jt][0];     dr[jt][3] = dr[jt][1];
        float2 b0n = *(const float2*)&bl[64 + col];
        dxn[jt][0] = b0n.x; dxn[jt][1] = b0n.y; dxn[jt][2] = b0n.x; dxn[jt][3] = b0n.y;
        float2 b1n = *(const float2*)&bl[160 + col];
        dhn[jt][0] = b1n.x; dhn[jt][1] = b1n.y; dhn[jt][2] = b1n.x; dhn[jt][3] = b1n.y;
    }

#pragma unroll
    for (int jt = 0; jt < 4; jt++)
#pragma unroll
        for (int kt = 0; kt < 4; kt++) {
            float2 bw; unsigned bh0, bl0, bh1, bl1;
            bw = sWl[(jt * 4 + kt) * 32 + lane];
            tf32_split(bw.x, bh0, bl0); tf32_split(bw.y, bh1, bl1);
            mma_tf32(dz[jt], xh[kt], bh0, bh1);
            mma_tf32(dz[jt], xlo[kt], bh0, bh1);
            mma_tf32(dz[jt], xh[kt], bl0, bl1);
            bw = sUl[(jt * 4 + kt) * 32 + lane];
            tf32_split(bw.x, bh0, bl0); tf32_split(bw.y, bh1, bl1);
            mma_tf32(dz[jt], hh[kt], bh0, bh1);
            mma_tf32(dz[jt], hlo[kt], bh0, bh1);
            mma_tf32(dz[jt], hh[kt], bl0, bl1);
            bw = sWl[((4 + jt) * 4 + kt) * 32 + lane];
            tf32_split(bw.x, bh0, bl0); tf32_split(bw.y, bh1, bl1);
            mma_tf32(dr[jt], xh[kt], bh0, bh1);
            mma_tf32(dr[jt], xlo[kt], bh0, bh1);
            mma_tf32(dr[jt], xh[kt], bl0, bl1);
            bw = sUl[((4 + jt) * 4 + kt) * 32 + lane];
            tf32_split(bw.x, bh0, bl0); tf32_split(bw.y, bh1, bl1);
            mma_tf32(dr[jt], hh[kt], bh0, bh1);
            mma_tf32(dr[jt], hlo[kt], bh0, bh1);
            mma_tf32(dr[jt], hh[kt], bl0, bl1);
            bw = sWl[((8 + jt) * 4 + kt) * 32 + lane];
            tf32_split(bw.x, bh0, bl0); tf32_split(bw.y, bh1, bl1);
            mma_tf32(dxn[jt], xh[kt], bh0, bh1);
            mma_tf32(dxn[jt], xlo[kt], bh0, bh1);
            mma_tf32(dxn[jt], xh[kt], bl0, bl1);
            bw = sUl[((8 + jt) * 4 + kt) * 32 + lane];
            tf32_split(bw.x, bh0, bl0); tf32_split(bw.y, bh1, bl1);
            mma_tf32(dhn[jt], hh[kt], bh0, bh1);
            mma_tf32(dhn[jt], hlo[kt], bh0, bh1);
            mma_tf32(dhn[jt], hh[kt], bl0, bl1);
        }

    float h2[4][4];
#pragma unroll
    for (int jt = 0; jt < 4; jt++) {
        int col = 8 * jt + 2 * m;
        float2 hA = *(const float2*)&g_link_state[lA * DD + col];
        float2 hB = *(const float2*)&g_link_state[lB * DD + col];
        float hd[4] = {hA.x, hA.y, hB.x, hB.y};
#pragma unroll
        for (int e = 0; e < 4; e++) {
            float z = fsig(dz[jt][e]);
            float r = fsig(dr[jt][e]);
            float n = ftanhf_(fmaf(r, dhn[jt][e], dxn[jt][e]));
            h2[jt][e] = fmaf(z, hd[e] - n, n);
        }
        *(float2*)&g_link_state[lA * DD + col] = make_float2(h2[jt][0], h2[jt][1]);
        *(float2*)&g_link_state[lB * DD + col] = make_float2(h2[jt][2], h2[jt][3]);
        *(float2*)&g_m[lA * DD + col] = make_float2(0.0f, 0.0f);
        *(float2*)&g_m[lB * DD + col] = make_float2(0.0f, 0.0f);
    }

    int src0 = (lane & ~3) | (m >> 1);
    int src1 = src0 + 2;
    bool odd = (m & 1);
    unsigned ah[4][4], al[4][4];
#pragma unroll
    for (int kt = 0; kt < 4; kt++) {
        float v[4];
        float s00 = __shfl_sync(0xffffffffu, h2[kt][0], src0);
        float s01 = __shfl_sync(0xffffffffu, h2[kt][1], src0);
        v[0] = odd ? s01 : s00;
        float s10 = __shfl_sync(0xffffffffu, h2[kt][2], src0);
        float s11 = __shfl_sync(0xffffffffu, h2[kt][3], src0);
        v[1] = odd ? s11 : s10;
        float s20 = __shfl_sync(0xffffffffu, h2[kt][0], src1);
        float s21 = __shfl_sync(0xffffffffu, h2[kt][1], src1);
        v[2] = odd ? s21 : s20;
        float s30 = __shfl_sync(0xffffffffu, h2[kt][2], src1);
        float s31 = __shfl_sync(0xffffffffu, h2[kt][3], src1);
        v[3] = odd ? s31 : s30;
#pragma unroll
        for (int e = 0; e < 4; e++) tf32_split(v[e], ah[kt][e], al[kt][e]);
    }
#pragma unroll
    for (int nt = 0; nt < 12; nt++) {
        float d2[4];
        int col = nt * 8 + 2 * m;
        float2 b = *(const float2*)&bp[col];
        d2[0] = b.x; d2[1] = b.y; d2[2] = b.x; d2[3] = b.y;
#pragma unroll
        for (int kt = 0; kt < 4; kt++) {
            float2 bw = sWp[(nt * 4 + kt) * 32 + lane];
            unsigned bh0, bl0, bh1, bl1;
            tf32_split(bw.x, bh0, bl0); tf32_split(bw.y, bh1, bl1);
            mma_tf32(d2, ah[kt], bh0, bh1);
            mma_tf32(d2, al[kt], bh0, bh1);
            mma_tf32(d2, ah[kt], bl0, bl1);
        }
        *(float2*)&g_lg[lA * 96 + col] = make_float2(d2[0], d2[1]);
        *(float2*)&g_lg[lB * 96 + col] = make_float2(d2[2], d2[3]);
    }
}

// ---------------------------------------------------------------------------
// Readout layer 1: H1 = selu(PS @ R1 + b1), stored fp16.
__global__ void __launch_bounds__(256)
readout1_kernel(const float* __restrict__ R1, const float* __restrict__ Rb1) {
    __shared__ float2 sB[32 * 4 * 32];

    int lane = threadIdx.x & 31;
    for (int idx = threadIdx.x; idx < 32 * 4 * 32; idx += blockDim.x) {
        int li = idx & 31;
        int t = idx >> 5;
        int nt = t >> 2, kt = t & 3;
        int gi = li >> 2, mi = li & 3;
        sB[idx] = make_float2(__ldg(&R1[(kt * 8 + mi)     * RUN + nt * 8 + gi]),
                              __ldg(&R1[(kt * 8 + mi + 4) * RUN + nt * 8 + gi]));
    }
    __syncthreads();

    int wid = (blockIdx.x * blockDim.x + threadIdx.x) >> 5;
    int p0 = wid * 16;
    if (p0 >= PN) return;
    int g = lane >> 2, m = lane & 3;
    int pA = p0 + g, pB = p0 + g + 8;

    unsigned ah[4][4], al[4][4];
#pragma unroll
    for (int kt = 0; kt < 4; kt++) {
        tf32_split(__ldg(&g_path_state[pA * DD + kt * 8 + m]),     ah[kt][0], al[kt][0]);
        tf32_split(__ldg(&g_path_state[pB * DD + kt * 8 + m]),     ah[kt][1], al[kt][1]);
        tf32_split(__ldg(&g_path_state[pA * DD + kt * 8 + m + 4]), ah[kt][2], al[kt][2]);
        tf32_split(__ldg(&g_path_state[pB * DD + kt * 8 + m + 4]), ah[kt][3], al[kt][3]);
    }

#pragma unroll 1
    for (int half = 0; half < 2; half++) {
        float d[16][4];
#pragma unroll
        for (int ntl = 0; ntl < 16; ntl++) {
            int col = (half * 16 + ntl) * 8 + 2 * m;
            float2 b = *(const float2*)&Rb1[col];
            d[ntl][0] = b.x; d[ntl][1] = b.y; d[ntl][2] = b.x; d[ntl][3] = b.y;
        }
#pragma unroll
        for (int ntl = 0; ntl < 16; ntl++) {
            int nt = half * 16 + ntl;
#pragma unroll
            for (int kt = 0; kt < 4; kt++) {
                float2 b = sB[(nt * 4 + kt) * 32 + lane];
                unsigned bh0, bl0, bh1, bl1;
                tf32_split(b.x, bh0, bl0);
                tf32_split(b.y, bh1, bl1);
                mma_tf32(d[ntl], ah[kt], bh0, bh1);
                mma_tf32(d[ntl], al[kt], bh0, bh1);
                mma_tf32(d[ntl], ah[kt], bl0, bl1);
            }
        }
#pragma unroll
        for (int ntl = 0; ntl < 16; ntl++) {
            int col = (half * 16 + ntl) * 8 + 2 * m;
            *(__half2*)&g_h1[pA * RUN + col] =
                __floats2half2_rn(fselu(d[ntl][0]), fselu(d[ntl][1]));
            *(__half2*)&g_h1[pB * RUN + col] =
                __floats2half2_rn(fselu(d[ntl][2]), fselu(d[ntl][3]));
        }
    }
}

// ---------------------------------------------------------------------------
// Readout layers 2+3: out = selu(H1 @ R2 + b2) @ R3 + b3. A fp16-exact in tf32.
__global__ void __launch_bounds__(256)
readout2_kernel(const float* __restrict__ R2, const float* __restrict__ Rb2,
                const float* __restrict__ R3, const float* __restrict__ Rb3,
                float* __restrict__ out) {
    __shared__ float2 sB[16 * 8 * 32];

    int lane = threadIdx.x & 31;
    int wid = (blockIdx.x * blockDim.x + threadIdx.x) >> 5;
    int p0 = wid * 16;
    bool active = (p0 < PN);
    int g = lane >> 2, m = lane & 3;
    int pA = p0 + g, pB = p0 + g + 8;

    float accA = 0.0f, accB = 0.0f;

#pragma unroll 1
    for (int half = 0; half < 2; half++) {
        float d[16][4];
        if (active) {
#pragma unroll
            for (int ntl = 0; ntl < 16; ntl++) {
                int col = half * 128 + ntl * 8 + 2 * m;
                float2 b = *(const float2*)&Rb2[col];
                d[ntl][0] = b.x; d[ntl][1] = b.y; d[ntl][2] = b.x; d[ntl][3] = b.y;
            }
        }
#pragma unroll 1
        for (int kc = 0; kc < 4; kc++) {
            __syncthreads();
            for (int idx = threadIdx.x; idx < 16 * 8 * 32; idx += blockDim.x) {
                int li = idx & 31;
                int t = idx >> 5;
                int ntl = t >> 3, kt = t & 7;
                int gi = li >> 2, mi = li & 3;
                int krow = kc * 64 + kt * 8;
                int col = half * 128 + ntl * 8 + gi;
                sB[idx] = make_float2(__ldg(&R2[(krow + mi)     * RUN + col]),
                                      __ldg(&R2[(krow + mi + 4) * RUN + col]));
            }
            __syncthreads();
            if (!active) continue;

            unsigned a[8][4];
#pragma unroll
            for (int kt = 0; kt < 8; kt++) {
                int k0 = kc * 64 + kt * 8;
                a[kt][0] = cvt_tf32(__half2float(g_h1[pA * RUN + k0 + m]));
                a[kt][1] = cvt_tf32(__half2float(g_h1[pB * RUN + k0 + m]));
                a[kt][2] = cvt_tf32(__half2float(g_h1[pA * RUN + k0 + m + 4]));
                a[kt][3] = cvt_tf32(__half2float(g_h1[pB * RUN + k0 + m + 4]));
            }
#pragma unroll
            for (int ntl = 0; ntl < 16; ntl++)
#pragma unroll
                for (int kt = 0; kt < 8; kt++) {
                    float2 b = sB[(ntl * 8 + kt) * 32 + lane];
                    unsigned bh0, bl0, bh1, bl1;
                    tf32_split(b.x, bh0, bl0);
                    tf32_split(b.y, bh1, bl1);
                    mma_tf32(d[ntl], a[kt], bh0, bh1);
                    mma_tf32(d[ntl], a[kt], bl0, bl1);
                }
        }
        if (active) {
#pragma unroll
            for (int ntl = 0; ntl < 16; ntl++) {
                int col = half * 128 + ntl * 8 + 2 * m;
                float2 r3 = *(const float2*)&R3[col];
                accA = fmaf(fselu(d[ntl][0]), r3.x, accA);
                accA = fmaf(fselu(d[ntl][1]), r3.y, accA);
                accB = fmaf(fselu(d[ntl][2]), r3.x, accB);
                accB = fmaf(fselu(d[ntl][3]), r3.y, accB);
            }
        }
    }

    if (active) {
        accA += __shfl_xor_sync(0xffffffffu, accA, 1);
        accA += __shfl_xor_sync(0xffffffffu, accA, 2);
        accB += __shfl_xor_sync(0xffffffffu, accB, 1);
        accB += __shfl_xor_sync(0xffffffffu, accB, 2);
        if (m == 0) {
            float b3 = __ldg(&Rb3[0]);
            out[pA] = accA + b3;
            out[pB] = accB + b3;
        }
    }
}

// ---------------------------------------------------------------------------
extern "C" void kernel_launch(void* const* d_in, const int* in_sizes, int n_in,
                              void* d_out, int out_size) {
    const int*   links = (const int*)d_in[0];
    const float* cap = (const float*)d_in[3];
    const float* pol = (const float*)d_in[4];
    const float* wt  = (const float*)d_in[5];
    const float* bw  = (const float*)d_in[6];
    const float* tos = (const float*)d_in[7];
    const float* pk  = (const float*)d_in[8];
    const float* avg = (const float*)d_in[9];
    const float* Wp  = (const float*)d_in[10];
    const float* Up  = (const float*)d_in[11];
    const float* bp  = (const float*)d_in[12];
    const float* Wl  = (const float*)d_in[13];
    const float* Ul  = (const float*)d_in[14];
    const float* bl  = (const float*)d_in[15];
    const float* R1  = (const float*)d_in[16];
    const float* Rb1 = (const float*)d_in[17];
    const float* R2  = (const float*)d_in[18];
    const float* Rb2 = (const float*)d_in[19];
    const float* R3  = (const float*)d_in[20];
    const float* Rb3 = (const float*)d_in[21];
    float* out = (float*)d_out;

    init_all_kernel<<<(PN * DD + 255) / 256, 256>>>(bw, tos, pk, avg, cap, pol, wt, Wp, bp);

    int nwarps = (PN + 15) / 16;               // 6250
    int pblocks = (nwarps + 3) / 4;            // 128 threads = 4 warps per block
    int lwarps = (NLK + 15) / 16;              // 625
    int lblocks = (lwarps + 3) / 4;            // 157
    for (int t = 0; t < TT; t++) {
        path_mma_kernel<<<pblocks, 128>>>(links, Up, bp, t < TT - 1 ? 1 : 0);
        if (t < TT - 1)
            link_mma_kernel<<<lblocks, 128>>>(Wl, Ul, bl, Wp, bp);
    }

    int rblocks = (nwarps + 7) / 8;            // 256 threads = 8 warps per block
    readout1_kernel<<<rblocks, 256>>>(R1, Rb1);
    readout2_kernel<<<rblocks, 256>>>(R2, Rb2, R3, Rb3, out);
}

// round 14
// speedup vs baseline: 1.0399x; 1.0014x over previous
#include <cuda_runtime.h>
#include <cuda_fp16.h>
#include <cstdint>

#define PN 100000
#define LLEN 5
#define NLK 10000
#define DD 32
#define TT 8
#define RUN 256

// Scratch (no allocations allowed)
__device__ float g_path_state[PN * DD];        // 12.8 MB
__device__ float g_link_state[NLK * DD];       // 1.28 MB
__device__ float g_lg[NLK * 3 * DD];           // 3.84 MB
__device__ float g_m[NLK * DD];                // 1.28 MB
__device__ __half g_h1[PN * RUN];              // 51.2 MB : readout hidden 1 (fp16)

__device__ __forceinline__ float fexp2(float x) {
    float r; asm("ex2.approx.f32 %0, %1;" : "=f"(r) : "f"(x)); return r;
}
__device__ __forceinline__ float frcp(float x) {
    float r; asm("rcp.approx.f32 %0, %1;" : "=f"(r) : "f"(x)); return r;
}
__device__ __forceinline__ float fsig(float x) {
    return frcp(1.0f + fexp2(-1.4426950408889634f * x));
}
__device__ __forceinline__ float ftanhf_(float x) {
    float e = fexp2(-2.8853900817779268f * x);
    return fmaf(2.0f, frcp(1.0f + e), -1.0f);
}
__device__ __forceinline__ float fselu(float x) {
    const float sc = 1.0507009873554805f;
    const float sa = 1.7580993408473768f;
    float neg = sa * (fexp2(1.4426950408889634f * x) - 1.0f);
    return x > 0.0f ? sc * x : neg;
}
__device__ __forceinline__ unsigned cvt_tf32(float f) {
    unsigned u; asm("cvt.rna.tf32.f32 %0, %1;" : "=r"(u) : "f"(f)); return u;
}
__device__ __forceinline__ void mma_tf32(float d[4], const unsigned a[4], const unsigned b0,
                                         const unsigned b1) {
    asm volatile(
        "mma.sync.aligned.m16n8k8.row.col.f32.tf32.tf32.f32 "
        "{%0,%1,%2,%3},{%4,%5,%6,%7},{%8,%9},{%0,%1,%2,%3};"
        : "+f"(d[0]), "+f"(d[1]), "+f"(d[2]), "+f"(d[3])
        : "r"(a[0]), "r"(a[1]), "r"(a[2]), "r"(a[3]), "r"(b0), "r"(b1));
}
__device__ __forceinline__ void tf32_split(float v, unsigned& hi, unsigned& lo) {
    hi = cvt_tf32(v);
    lo = cvt_tf32(v - __uint_as_float(hi));
}
__device__ __forceinline__ void mma3(float d[4], const unsigned ah[4], const unsigned al[4],
                                     uint4 b) {
    mma_tf32(d, ah, b.x, b.y);
    mma_tf32(d, al, b.x, b.y);
    mma_tf32(d, ah, b.z, b.w);
}
// 2x compensation with hi-only fragment: d += (ah + al) * bh.
__device__ __forceinline__ void mma2h(float d[4], const unsigned ah[4], const unsigned al[4],
                                      uint2 b) {
    mma_tf32(d, ah, b.x, b.y);
    mma_tf32(d, al, b.x, b.y);
}

// ---------------------------------------------------------------------------
// Merged init (one launch): path-state init + link-state/lg/m init.
__global__ void init_all_kernel(const float* __restrict__ bw, const float* __restrict__ tos,
                                const float* __restrict__ pk, const float* __restrict__ avg,
                                const float* __restrict__ cap, const float* __restrict__ pol,
                                const float* __restrict__ wt,
                                const float* __restrict__ Wp, const float* __restrict__ bp) {
    int i = blockIdx.x * blockDim.x + threadIdx.x;
    if (i < PN * DD) {
        int p = i >> 5, c = i & 31;
        float v = 0.0f;
        if (c == 0) v = bw[p];
        else if (c == 1) v = tos[p];
        else if (c == 2) v = pk[p];
        else if (c == 3) v = avg[p];
        g_path_state[i] = v;
    }
    int w = i >> 5;
    int lane = i & 31;
    if (w < NLK) {
        float c0 = __ldg(&cap[w]), c1 = __ldg(&pol[w]), c2 = __ldg(&wt[w]);
        float v = (lane == 0) ? c0 : (lane == 1) ? c1 : (lane == 2) ? c2 : 0.0f;
        g_link_state[w * DD + lane] = v;
        g_m[w * DD + lane] = 0.0f;
#pragma unroll
        for (int g = 0; g < 3; g++) {
            int c = g * 32 + lane;
            float o = __ldg(&bp[c]);
            o = fmaf(c0, __ldg(&Wp[c]),       o);
            o = fmaf(c1, __ldg(&Wp[96 + c]),  o);
            o = fmaf(c2, __ldg(&Wp[192 + c]), o);
            g_lg[w * 96 + c] = o;
        }
    }
}

// ---------------------------------------------------------------------------
// Path phase via tensor cores. Occupancy push: recurrent-bias and link-index
// hoists dropped (both re-load from L1-resident lines per step), freeing ~22
// regs; __launch_bounds__(128,4) targets 4 CTAs/SM (was 3 at regs=146).
// z/r fragments hi-only uint2, n fragments uint4 (R13-proven LDS cut).
__global__ void __launch_bounds__(128, 4)
path_mma_kernel(const int* __restrict__ links, const float* __restrict__ Up,
                const float* __restrict__ bp, int do_scatter) {
    __shared__ uint2 sBzr[32 * 32];   // z/r tiles: [(nt*4+kt)*32 + lane] = {hi0, hi1}
    __shared__ uint4 sBn[16 * 32];    // n tiles: [((nt-8)*4+kt)*32 + lane]

    int lane = threadIdx.x & 31;

    // Stage z/r (hi only)
    for (int idx = threadIdx.x; idx < 32 * 32; idx += blockDim.x) {
        int li = idx & 31;
        int t = idx >> 5;             // nt*4 + kt, nt in [0,8)
        int nt = t >> 2, kt = t & 3;
        int gi = li >> 2, mi = li & 3;
        unsigned h0 = cvt_tf32(__ldg(&Up[(kt * 8 + mi)     * 96 + nt * 8 + gi]));
        unsigned h1 = cvt_tf32(__ldg(&Up[(kt * 8 + mi + 4) * 96 + nt * 8 + gi]));
        sBzr[idx] = make_uint2(h0, h1);
    }
    // Stage n (hi + lo)
    for (int idx = threadIdx.x; idx < 16 * 32; idx += blockDim.x) {
        int li = idx & 31;
        int t = idx >> 5;             // (nt-8)*4 + kt
        int nt = (t >> 2) + 8, kt = t & 3;
        int gi = li >> 2, mi = li & 3;
        unsigned h0, l0, h1, l1;
        tf32_split(__ldg(&Up[(kt * 8 + mi)     * 96 + nt * 8 + gi]), h0, l0);
        tf32_split(__ldg(&Up[(kt * 8 + mi + 4) * 96 + nt * 8 + gi]), h1, l1);
        sBn[idx] = make_uint4(h0, h1, l0, l1);
    }
    __syncthreads();

    int wid = (blockIdx.x * blockDim.x + threadIdx.x) >> 5;
    int p0 = wid * 16;
    if (p0 >= PN) return;
    int g = lane >> 2, m = lane & 3;
    int pA = p0 + g, pB = p0 + g + 8;

    float h[4][4];
#pragma unroll
    for (int jt = 0; jt < 4; jt++) {
        float2 ha = *(const float2*)&g_path_state[pA * DD + 8 * jt + 2 * m];
        float2 hb = *(const float2*)&g_path_state[pB * DD + 8 * jt + 2 * m];
        h[jt][0] = ha.x; h[jt][1] = ha.y; h[jt][2] = hb.x; h[jt][3] = hb.y;
    }

    int src0 = (lane & ~3) | (m >> 1);
    int src1 = src0 + 2;
    bool odd = (m & 1);

#pragma unroll 1
    for (int s = 0; s < LLEN; s++) {
        // Per-step index loads (L1-resident after step 0; frees hoist regs)
        int lkA = __ldg(&links[pA * LLEN + s]);
        int lkB = __ldg(&links[pB * LLEN + s]);
        const float* lgA = g_lg + (size_t)lkA * 96;
        const float* lgB = g_lg + (size_t)lkB * 96;

        float2 xg[2][3][4];   // [path][gate][jt] — issued early, consumed post-mma
#pragma unroll
        for (int gate = 0; gate < 3; gate++)
#pragma unroll
            for (int jt = 0; jt < 4; jt++) {
                xg[0][gate][jt] = *(const float2*)&lgA[gate * 32 + 8 * jt + 2 * m];
                xg[1][gate][jt] = *(const float2*)&lgB[gate * 32 + 8 * jt + 2 * m];
            }

        float d[12][4];
#pragma unroll
        for (int nt = 0; nt < 12; nt++) {
            int gate = nt >> 2, jt = nt & 3;
            float2 br = *(const float2*)&bp[96 + gate * 32 + 8 * jt + 2 * m];
            d[nt][0] = br.x; d[nt][1] = br.y; d[nt][2] = br.x; d[nt][3] = br.y;
        }

#pragma unroll
        for (int kt = 0; kt < 4; kt++) {
            float v[4];
            float s00 = __shfl_sync(0xffffffffu, h[kt][0], src0);
            float s01 = __shfl_sync(0xffffffffu, h[kt][1], src0);
            v[0] = odd ? s01 : s00;
            float s10 = __shfl_sync(0xffffffffu, h[kt][2], src0);
            float s11 = __shfl_sync(0xffffffffu, h[kt][3], src0);
            v[1] = odd ? s11 : s10;
            float s20 = __shfl_sync(0xffffffffu, h[kt][0], src1);
            float s21 = __shfl_sync(0xffffffffu, h[kt][1], src1);
            v[2] = odd ? s21 : s20;
            float s30 = __shfl_sync(0xffffffffu, h[kt][2], src1);
            float s31 = __shfl_sync(0xffffffffu, h[kt][3], src1);
            v[3] = odd ? s31 : s30;
            unsigned ah[4], al[4];
#pragma unroll
            for (int e = 0; e < 4; e++) tf32_split(v[e], ah[e], al[e]);
#pragma unroll
            for (int nt = 0; nt < 8; nt++)
                mma2h(d[nt], ah, al, sBzr[(nt * 4 + kt) * 32 + lane]);
#pragma unroll
            for (int nt = 8; nt < 12; nt++)
                mma3(d[nt], ah, al, sBn[((nt - 8) * 4 + kt) * 32 + lane]);
        }

#pragma unroll
        for (int jt = 0; jt < 4; jt++) {
            float xz[4] = {xg[0][0][jt].x, xg[0][0][jt].y, xg[1][0][jt].x, xg[1][0][jt].y};
            float xr[4] = {xg[0][1][jt].x, xg[0][1][jt].y, xg[1][1][jt].x, xg[1][1][jt].y};
            float xn[4] = {xg[0][2][jt].x, xg[0][2][jt].y, xg[1][2][jt].x, xg[1][2][jt].y};
#pragma unroll
            for (int e = 0; e < 4; e++) {
                float z = fsig(d[jt][e] + xz[e]);
                float r = fsig(d[4 + jt][e] + xr[e]);
                float n = ftanhf_(fmaf(r, d[8 + jt][e], xn[e]));
                h[jt][e] = fmaf(z, h[jt][e] - n, n);
            }
            if (do_scatter) {
                int cA = 8 * jt + 2 * m;
                atomicAdd((float2*)&g_m[lkA * DD + cA], make_float2(h[jt][0], h[jt][1]));
                atomicAdd((float2*)&g_m[lkB * DD + cA], make_float2(h[jt][2], h[jt][3]));
            }
        }
    }

#pragma unroll
    for (int jt = 0; jt < 4; jt++) {
        *(float2*)&g_path_state[pA * DD + 8 * jt + 2 * m] = make_float2(h[jt][0], h[jt][1]);
        *(float2*)&g_path_state[pB * DD + 8 * jt + 2 * m] = make_float2(h[jt][2], h[jt][3]);
    }
}

// ---------------------------------------------------------------------------
// Link phase via tensor cores (3xTF32), R6-proven. Warp = 16 links.
__global__ void __launch_bounds__(128)
link_mma_kernel(const float* __restrict__ Wl, const float* __restrict__ Ul,
                const float* __restrict__ bl,
                const float* __restrict__ Wp, const float* __restrict__ bp) {
    __shared__ float2 sWl[48 * 32], sUl[48 * 32], sWp[48 * 32];   // 36KB

    int lane = threadIdx.x & 31;
    for (int idx = threadIdx.x; idx < 48 * 32; idx += blockDim.x) {
        int li = idx & 31;
        int t = idx >> 5;
        int nt = t >> 2, kt = t & 3;
        int gi = li >> 2, mi = li & 3;
        int r0 = (kt * 8 + mi) * 96 + nt * 8 + gi;
        int r1 = (kt * 8 + mi + 4) * 96 + nt * 8 + gi;
        sWl[idx] = make_float2(__ldg(&Wl[r0]), __ldg(&Wl[r1]));
        sUl[idx] = make_float2(__ldg(&Ul[r0]), __ldg(&Ul[r1]));
        sWp[idx] = make_float2(__ldg(&Wp[r0]), __ldg(&Wp[r1]));
    }
    __syncthreads();

    int wid = (blockIdx.x * blockDim.x + threadIdx.x) >> 5;
    int l0 = wid * 16;
    if (l0 >= NLK) return;
    int g = lane >> 2, m = lane & 3;
    int lA = l0 + g, lB = l0 + g + 8;

    unsigned xh[4][4], xlo[4][4], hh[4][4], hlo[4][4];
#pragma unroll
    for (int kt = 0; kt < 4; kt++) {
        tf32_split(g_m[lA * DD + kt * 8 + m],     xh[kt][0], xlo[kt][0]);
        tf32_split(g_m[lB * DD + kt * 8 + m],     xh[kt][1], xlo[kt][1]);
        tf32_split(g_m[lA * DD + kt * 8 + m + 4], xh[kt][2], xlo[kt][2]);
        tf32_split(g_m[lB * DD + kt * 8 + m + 4], xh[kt][3], xlo[kt][3]);
        tf32_split(g_link_state[lA * DD + kt * 8 + m],     hh[kt][0], hlo[kt][0]);
        tf32_split(g_link_state[lB * DD + kt * 8 + m],     hh[kt][1], hlo[kt][1]);
        tf32_split(g_link_state[lA * DD + kt * 8 + m + 4], hh[kt][2], hlo[kt][2]);
        tf32_split(g_link_state[lB * DD + kt * 8 + m + 4], hh[kt][3], hlo[kt][3]);
    }

    float dz[4][4], dr[4][4], dxn[4][4], dhn[4][4];
#pragma unroll
    for (int jt = 0; jt < 4; jt++) {
        int col = 8 * jt + 2 * m;
        float2 b0z = *(const float2*)&bl[col];
        float2 b1z = *(const float2*)&bl[96 + col];
        dz[jt][0] = b0z.x + b1z.x; dz[jt][1] = b0z.y + b1z.y;
        dz[jt][2] = dz[jt][0];     dz[jt][3] = dz[jt][1];
        float2 b0r = *(const float2*)&bl[32 + col];
        float2 b1r = *(const float2*)&bl[128 + col];
        dr[jt][0] = b0r.x + b1r.x; dr[jt][1] = b0r.y + b1r.y;
        dr[jt][2] = dr[jt][0];     dr[jt][3] = dr[jt][1];
        float2 b0n = *(const float2*)&bl[64 + col];
        dxn[jt][0] = b0n.x; dxn[jt][1] = b0n.y; dxn[jt][2] = b0n.x; dxn[jt][3] = b0n.y;
        float2 b1n = *(const float2*)&bl[160 + col];
        dhn[jt][0] = b1n.x; dhn[jt][1] = b1n.y; dhn[jt][2] = b1n.x; dhn[jt][3] = b1n.y;
    }

#pragma unroll
    for (int jt = 0; jt < 4; jt++)
#pragma unroll
        for (int kt = 0; kt < 4; kt++) {
            float2 bw; unsigned bh0, bl0, bh1, bl1;
            bw = sWl[(jt * 4 + kt) * 32 + lane];
            tf32_split(bw.x, bh0, bl0); tf32_split(bw.y, bh1, bl1);
            mma_tf32(dz[jt], xh[kt], bh0, bh1);
            mma_tf32(dz[jt], xlo[kt], bh0, bh1);
            mma_tf32(dz[jt], xh[kt], bl0, bl1);
            bw = sUl[(jt * 4 + kt) * 32 + lane];
            tf32_split(bw.x, bh0, bl0); tf32_split(bw.y, bh1, bl1);
            mma_tf32(dz[jt], hh[kt], bh0, bh1);
            mma_tf32(dz[jt], hlo[kt], bh0, bh1);
            mma_tf32(dz[jt], hh[kt], bl0, bl1);
            bw = sWl[((4 + jt) * 4 + kt) * 32 + lane];
            tf32_split(bw.x, bh0, bl0); tf32_split(bw.y, bh1, bl1);
            mma_tf32(dr[jt], xh[kt], bh0, bh1);
            mma_tf32(dr[jt], xlo[kt], bh0, bh1);
            mma_tf32(dr[jt], xh[kt], bl0, bl1);
            bw = sUl[((4 + jt) * 4 + kt) * 32 + lane];
            tf32_split(bw.x, bh0, bl0); tf32_split(bw.y, bh1, bl1);
            mma_tf32(dr[jt], hh[kt], bh0, bh1);
            mma_tf32(dr[jt], hlo[kt], bh0, bh1);
            mma_tf32(dr[jt], hh[kt], bl0, bl1);
            bw = sWl[((8 + jt) * 4 + kt) * 32 + lane];
            tf32_split(bw.x, bh0, bl0); tf32_split(bw.y, bh1, bl1);
            mma_tf32(dxn[jt], xh[kt], bh0, bh1);
            mma_tf32(dxn[jt], xlo[kt], bh0, bh1);
            mma_tf32(dxn[jt], xh[kt], bl0, bl1);
            bw = sUl[((8 + jt) * 4 + kt) * 32 + lane];
            tf32_split(bw.x, bh0, bl0); tf32_split(bw.y, bh1, bl1);
            mma_tf32(dhn[jt], hh[kt], bh0, bh1);
            mma_tf32(dhn[jt], hlo[kt], bh0, bh1);
            mma_tf32(dhn[jt], hh[kt], bl0, bl1);
        }

    float h2[4][4];
#pragma unroll
    for (int jt = 0; jt < 4; jt++) {
        int col = 8 * jt + 2 * m;
        float2 hA = *(const float2*)&g_link_state[lA * DD + col];
        float2 hB = *(const float2*)&g_link_state[lB * DD + col];
        float hd[4] = {hA.x, hA.y, hB.x, hB.y};
#pragma unroll
        for (int e = 0; e < 4; e++) {
            float z = fsig(dz[jt][e]);
            float r = fsig(dr[jt][e]);
            float n = ftanhf_(fmaf(r, dhn[jt][e], dxn[jt][e]));
            h2[jt][e] = fmaf(z, hd[e] - n, n);
        }
        *(float2*)&g_link_state[lA * DD + col] = make_float2(h2[jt][0], h2[jt][1]);
        *(float2*)&g_link_state[lB * DD + col] = make_float2(h2[jt][2], h2[jt][3]);
        *(float2*)&g_m[lA * DD + col] = make_float2(0.0f, 0.0f);
        *(float2*)&g_m[lB * DD + col] = make_float2(0.0f, 0.0f);
    }

    int src0 = (lane & ~3) | (m >> 1);
    int src1 = src0 + 2;
    bool odd = (m & 1);
    unsigned ah[4][4], al[4][4];
#pragma unroll
    for (int kt = 0; kt < 4; kt++) {
        float v[4];
        float s00 = __shfl_sync(0xffffffffu, h2[kt][0], src0);
        float s01 = __shfl_sync(0xffffffffu, h2[kt][1], src0);
        v[0] = odd ? s01 : s00;
        float s10 = __shfl_sync(0xffffffffu, h2[kt][2], src0);
        float s11 = __shfl_sync(0xffffffffu, h2[kt][3], src0);
        v[1] = odd ? s11 : s10;
        float s20 = __shfl_sync(0xffffffffu, h2[kt][0], src1);
        float s21 = __shfl_sync(0xffffffffu, h2[kt][1], src1);
        v[2] = odd ? s21 : s20;
        float s30 = __shfl_sync(0xffffffffu, h2[kt][2], src1);
        float s31 = __shfl_sync(0xffffffffu, h2[kt][3], src1);
        v[3] = odd ? s31 : s30;
#pragma unroll
        for (int e = 0; e < 4; e++) tf32_split(v[e], ah[kt][e], al[kt][e]);
    }
#pragma unroll
    for (int nt = 0; nt < 12; nt++) {
        float d2[4];
        int col = nt * 8 + 2 * m;
        float2 b = *(const float2*)&bp[col];
        d2[0] = b.x; d2[1] = b.y; d2[2] = b.x; d2[3] = b.y;
#pragma unroll
        for (int kt = 0; kt < 4; kt++) {
            float2 bw = sWp[(nt * 4 + kt) * 32 + lane];
            unsigned bh0, bl0, bh1, bl1;
            tf32_split(bw.x, bh0, bl0); tf32_split(bw.y, bh1, bl1);
            mma_tf32(d2, ah[kt], bh0, bh1);
            mma_tf32(d2, al[kt], bh0, bh1);
            mma_tf32(d2, ah[kt], bl0, bl1);
        }
        *(float2*)&g_lg[lA * 96 + col] = make_float2(d2[0], d2[1]);
        *(float2*)&g_lg[lB * 96 + col] = make_float2(d2[2], d2[3]);
    }
}

// ---------------------------------------------------------------------------
// Readout layer 1: H1 = selu(PS @ R1 + b1), stored fp16.
__global__ void __launch_bounds__(256)
readout1_kernel(const float* __restrict__ R1, const float* __restrict__ Rb1) {
    __shared__ float2 sB[32 * 4 * 32];

    int lane = threadIdx.x & 31;
    for (int idx = threadIdx.x; idx < 32 * 4 * 32; idx += blockDim.x) {
        int li = idx & 31;
        int t = idx >> 5;
        int nt = t >> 2, kt = t & 3;
        int gi = li >> 2, mi = li & 3;
        sB[idx] = make_float2(__ldg(&R1[(kt * 8 + mi)     * RUN + nt * 8 + gi]),
                              __ldg(&R1[(kt * 8 + mi + 4) * RUN + nt * 8 + gi]));
    }
    __syncthreads();

    int wid = (blockIdx.x * blockDim.x + threadIdx.x) >> 5;
    int p0 = wid * 16;
    if (p0 >= PN) return;
    int g = lane >> 2, m = lane & 3;
    int pA = p0 + g, pB = p0 + g + 8;

    unsigned ah[4][4], al[4][4];
#pragma unroll
    for (int kt = 0; kt < 4; kt++) {
        tf32_split(__ldg(&g_path_state[pA * DD + kt * 8 + m]),     ah[kt][0], al[kt][0]);
        tf32_split(__ldg(&g_path_state[pB * DD + kt * 8 + m]),     ah[kt][1], al[kt][1]);
        tf32_split(__ldg(&g_path_state[pA * DD + kt * 8 + m + 4]), ah[kt][2], al[kt][2]);
        tf32_split(__ldg(&g_path_state[pB * DD + kt * 8 + m + 4]), ah[kt][3], al[kt][3]);
    }

#pragma unroll 1
    for (int half = 0; half < 2; half++) {
        float d[16][4];
#pragma unroll
        for (int ntl = 0; ntl < 16; ntl++) {
            int col = (half * 16 + ntl) * 8 + 2 * m;
            float2 b = *(const float2*)&Rb1[col];
            d[ntl][0] = b.x; d[ntl][1] = b.y; d[ntl][2] = b.x; d[ntl][3] = b.y;
        }
#pragma unroll
        for (int ntl = 0; ntl < 16; ntl++) {
            int nt = half * 16 + ntl;
#pragma unroll
            for (int kt = 0; kt < 4; kt++) {
                float2 b = sB[(nt * 4 + kt) * 32 + lane];
                unsigned bh0, bl0, bh1, bl1;
                tf32_split(b.x, bh0, bl0);
                tf32_split(b.y, bh1, bl1);
                mma_tf32(d[ntl], ah[kt], bh0, bh1);
                mma_tf32(d[ntl], al[kt], bh0, bh1);
                mma_tf32(d[ntl], ah[kt], bl0, bl1);
            }
        }
#pragma unroll
        for (int ntl = 0; ntl < 16; ntl++) {
            int col = (half * 16 + ntl) * 8 + 2 * m;
            *(__half2*)&g_h1[pA * RUN + col] =
                __floats2half2_rn(fselu(d[ntl][0]), fselu(d[ntl][1]));
            *(__half2*)&g_h1[pB * RUN + col] =
                __floats2half2_rn(fselu(d[ntl][2]), fselu(d[ntl][3]));
        }
    }
}

// ---------------------------------------------------------------------------
// Readout layers 2+3: out = selu(H1 @ R2 + b2) @ R3 + b3. A fp16-exact in tf32.
__global__ void __launch_bounds__(256)
readout2_kernel(const float* __restrict__ R2, const float* __restrict__ Rb2,
                const float* __restrict__ R3, const float* __restrict__ Rb3,
                float* __restrict__ out) {
    __shared__ float2 sB[16 * 8 * 32];

    int lane = threadIdx.x & 31;
    int wid = (blockIdx.x * blockDim.x + threadIdx.x) >> 5;
    int p0 = wid * 16;
    bool active = (p0 < PN);
    int g = lane >> 2, m = lane & 3;
    int pA = p0 + g, pB = p0 + g + 8;

    float accA = 0.0f, accB = 0.0f;

#pragma unroll 1
    for (int half = 0; half < 2; half++) {
        float d[16][4];
        if (active) {
#pragma unroll
            for (int ntl = 0; ntl < 16; ntl++) {
                int col = half * 128 + ntl * 8 + 2 * m;
                float2 b = *(const float2*)&Rb2[col];
                d[ntl][0] = b.x; d[ntl][1] = b.y; d[ntl][2] = b.x; d[ntl][3] = b.y;
            }
        }
#pragma unroll 1
        for (int kc = 0; kc < 4; kc++) {
            __syncthreads();
            for (int idx = threadIdx.x; idx < 16 * 8 * 32; idx += blockDim.x) {
                int li = idx & 31;
                int t = idx >> 5;
                int ntl = t >> 3, kt = t & 7;
                int gi = li >> 2, mi = li & 3;
                int krow = kc * 64 + kt * 8;
                int col = half * 128 + ntl * 8 + gi;
                sB[idx] = make_float2(__ldg(&R2[(krow + mi)     * RUN + col]),
                                      __ldg(&R2[(krow + mi + 4) * RUN + col]));
            }
            __syncthreads();
            if (!active) continue;

            unsigned a[8][4];
#pragma unroll
            for (int kt = 0; kt < 8; kt++) {
                int k0 = kc * 64 + kt * 8;
                a[kt][0] = cvt_tf32(__half2float(g_h1[pA * RUN + k0 + m]));
                a[kt][1] = cvt_tf32(__half2float(g_h1[pB * RUN + k0 + m]));
                a[kt][2] = cvt_tf32(__half2float(g_h1[pA * RUN + k0 + m + 4]));
                a[kt][3] = cvt_tf32(__half2float(g_h1[pB * RUN + k0 + m + 4]));
            }
#pragma unroll
            for (int ntl = 0; ntl < 16; ntl++)
#pragma unroll
                for (int kt = 0; kt < 8; kt++) {
                    float2 b = sB[(ntl * 8 + kt) * 32 + lane];
                    unsigned bh0, bl0, bh1, bl1;
                    tf32_split(b.x, bh0, bl0);
                    tf32_split(b.y, bh1, bl1);
                    mma_tf32(d[ntl], a[kt], bh0, bh1);
                    mma_tf32(d[ntl], a[kt], bl0, bl1);
                }
        }
        if (active) {
#pragma unroll
            for (int ntl = 0; ntl < 16; ntl++) {
                int col = half * 128 + ntl * 8 + 2 * m;
                float2 r3 = *(const float2*)&R3[col];
                accA = fmaf(fselu(d[ntl][0]), r3.x, accA);
                accA = fmaf(fselu(d[ntl][1]), r3.y, accA);
                accB = fmaf(fselu(d[ntl][2]), r3.x, accB);
                accB = fmaf(fselu(d[ntl][3]), r3.y, accB);
            }
        }
    }

    if (active) {
        accA += __shfl_xor_sync(0xffffffffu, accA, 1);
        accA += __shfl_xor_sync(0xffffffffu, accA, 2);
        accB += __shfl_xor_sync(0xffffffffu, accB, 1);
        accB += __shfl_xor_sync(0xffffffffu, accB, 2);
        if (m == 0) {
            float b3 = __ldg(&Rb3[0]);
            out[pA] = accA + b3;
            out[pB] = accB + b3;
        }
    }
}

// ---------------------------------------------------------------------------
extern "C" void kernel_launch(void* const* d_in, const int* in_sizes, int n_in,
                              void* d_out, int out_size) {
    const int*   links = (const int*)d_in[0];
    const float* cap = (const float*)d_in[3];
    const float* pol = (const float*)d_in[4];
    const float* wt  = (const float*)d_in[5];
    const float* bw  = (const float*)d_in[6];
    const float* tos = (const float*)d_in[7];
    const float* pk  = (const float*)d_in[8];
    const float* avg = (const float*)d_in[9];
    const float* Wp  = (const float*)d_in[10];
    const float* Up  = (const float*)d_in[11];
    const float* bp  = (const float*)d_in[12];
    const float* Wl  = (const float*)d_in[13];
    const float* Ul  = (const float*)d_in[14];
    const float* bl  = (const float*)d_in[15];
    const float* R1  = (const float*)d_in[16];
    const float* Rb1 = (const float*)d_in[17];
    const float* R2  = (const float*)d_in[18];
    const float* Rb2 = (const float*)d_in[19];
    const float* R3  = (const float*)d_in[20];
    const float* Rb3 = (const float*)d_in[21];
    float* out = (float*)d_out;

    init_all_kernel<<<(PN * DD + 255) / 256, 256>>>(bw, tos, pk, avg, cap, pol, wt, Wp, bp);

    int nwarps = (PN + 15) / 16;               // 6250
    int pblocks = (nwarps + 3) / 4;            // 128 threads = 4 warps per block
    int lwarps = (NLK + 15) / 16;              // 625
    int lblocks = (lwarps + 3) / 4;            // 157
    for (int t = 0; t < TT; t++) {
        path_mma_kernel<<<pblocks, 128>>>(links, Up, bp, t < TT - 1 ? 1 : 0);
        if (t < TT - 1)
            link_mma_kernel<<<lblocks, 128>>>(Wl, Ul, bl, Wp, bp);
    }

    int rblocks = (nwarps + 7) / 8;            // 256 threads = 8 warps per block
    readout1_kernel<<<rblocks, 256>>>(R1, Rb1);
    readout2_kernel<<<rblocks, 256>>>(R2, Rb2, R3, Rb3, out);
}

// round 15
// speedup vs baseline: 1.0835x; 1.0419x over previous
#include <cuda_runtime.h>
#include <cuda_fp16.h>
#include <cstdint>

#define PN 100000
#define LLEN 5
#define NLK 10000
#define DD 32
#define TT 8
#define RUN 256

// Scratch (no allocations allowed)
__device__ float g_path_state[PN * DD];        // 12.8 MB
__device__ float g_link_state[NLK * DD];       // 1.28 MB
__device__ float g_lg[NLK * 3 * DD];           // 3.84 MB (z/r cols carry b0+b1 folded)
__device__ float g_m[NLK * DD];                // 1.28 MB
__device__ __half g_h1[PN * RUN];              // 51.2 MB : readout hidden 1 (fp16)

__device__ __forceinline__ float fexp2(float x) {
    float r; asm("ex2.approx.f32 %0, %1;" : "=f"(r) : "f"(x)); return r;
}
__device__ __forceinline__ float frcp(float x) {
    float r; asm("rcp.approx.f32 %0, %1;" : "=f"(r) : "f"(x)); return r;
}
__device__ __forceinline__ float fsig(float x) {
    return frcp(1.0f + fexp2(-1.4426950408889634f * x));
}
__device__ __forceinline__ float ftanhf_(float x) {
    float e = fexp2(-2.8853900817779268f * x);
    return fmaf(2.0f, frcp(1.0f + e), -1.0f);
}
__device__ __forceinline__ float fselu(float x) {
    const float sc = 1.0507009873554805f;
    const float sa = 1.7580993408473768f;
    float neg = sa * (fexp2(1.4426950408889634f * x) - 1.0f);
    return x > 0.0f ? sc * x : neg;
}
__device__ __forceinline__ unsigned cvt_tf32(float f) {
    unsigned u; asm("cvt.rna.tf32.f32 %0, %1;" : "=r"(u) : "f"(f)); return u;
}
__device__ __forceinline__ void mma_tf32(float d[4], const unsigned a[4], const unsigned b0,
                                         const unsigned b1) {
    asm volatile(
        "mma.sync.aligned.m16n8k8.row.col.f32.tf32.tf32.f32 "
        "{%0,%1,%2,%3},{%4,%5,%6,%7},{%8,%9},{%0,%1,%2,%3};"
        : "+f"(d[0]), "+f"(d[1]), "+f"(d[2]), "+f"(d[3])
        : "r"(a[0]), "r"(a[1]), "r"(a[2]), "r"(a[3]), "r"(b0), "r"(b1));
}
__device__ __forceinline__ void tf32_split(float v, unsigned& hi, unsigned& lo) {
    hi = cvt_tf32(v);
    lo = cvt_tf32(v - __uint_as_float(hi));
}
__device__ __forceinline__ void mma3(float d[4], const unsigned ah[4], const unsigned al[4],
                                     uint4 b) {
    mma_tf32(d, ah, b.x, b.y);
    mma_tf32(d, al, b.x, b.y);
    mma_tf32(d, ah, b.z, b.w);
}
// 2x compensation with hi-only fragment: d += (ah + al) * bh.
__device__ __forceinline__ void mma2h(float d[4], const unsigned ah[4], const unsigned al[4],
                                      uint2 b) {
    mma_tf32(d, ah, b.x, b.y);
    mma_tf32(d, al, b.x, b.y);
}

// ---------------------------------------------------------------------------
// Merged init. g_lg z/r columns (c<64) get BOTH biases folded (b0 + b1),
// removing the per-step recurrent z/r bias loads from the path kernel.
__global__ void init_all_kernel(const float* __restrict__ bw, const float* __restrict__ tos,
                                const float* __restrict__ pk, const float* __restrict__ avg,
                                const float* __restrict__ cap, const float* __restrict__ pol,
                                const float* __restrict__ wt,
                                const float* __restrict__ Wp, const float* __restrict__ bp) {
    int i = blockIdx.x * blockDim.x + threadIdx.x;
    if (i < PN * DD) {
        int p = i >> 5, c = i & 31;
        float v = 0.0f;
        if (c == 0) v = bw[p];
        else if (c == 1) v = tos[p];
        else if (c == 2) v = pk[p];
        else if (c == 3) v = avg[p];
        g_path_state[i] = v;
    }
    int w = i >> 5;
    int lane = i & 31;
    if (w < NLK) {
        float c0 = __ldg(&cap[w]), c1 = __ldg(&pol[w]), c2 = __ldg(&wt[w]);
        float v = (lane == 0) ? c0 : (lane == 1) ? c1 : (lane == 2) ? c2 : 0.0f;
        g_link_state[w * DD + lane] = v;
        g_m[w * DD + lane] = 0.0f;
#pragma unroll
        for (int g = 0; g < 3; g++) {
            int c = g * 32 + lane;
            float o = __ldg(&bp[c]);
            if (g < 2) o += __ldg(&bp[96 + c]);   // fold recurrent z/r bias
            o = fmaf(c0, __ldg(&Wp[c]),       o);
            o = fmaf(c1, __ldg(&Wp[96 + c]),  o);
            o = fmaf(c2, __ldg(&Wp[192 + c]), o);
            g_lg[w * 96 + c] = o;
        }
    }
}

// ---------------------------------------------------------------------------
// Path phase via tensor cores (L1-throughput-bound; traffic minimized).
// z/r accumulators init to ZERO (biases folded into g_lg); only the 4 n-gate
// recurrent bias loads remain per step. z/r B fragments hi-only uint2.
__global__ void __launch_bounds__(128, 4)
path_mma_kernel(const int* __restrict__ links, const float* __restrict__ Up,
                const float* __restrict__ bp, int do_scatter) {
    __shared__ uint2 sBzr[32 * 32];   // z/r tiles: [(nt*4+kt)*32 + lane] = {hi0, hi1}
    __shared__ uint4 sBn[16 * 32];    // n tiles: [((nt-8)*4+kt)*32 + lane]

    int lane = threadIdx.x & 31;

    for (int idx = threadIdx.x; idx < 32 * 32; idx += blockDim.x) {
        int li = idx & 31;
        int t = idx >> 5;
        int nt = t >> 2, kt = t & 3;
        int gi = li >> 2, mi = li & 3;
        unsigned h0 = cvt_tf32(__ldg(&Up[(kt * 8 + mi)     * 96 + nt * 8 + gi]));
        unsigned h1 = cvt_tf32(__ldg(&Up[(kt * 8 + mi + 4) * 96 + nt * 8 + gi]));
        sBzr[idx] = make_uint2(h0, h1);
    }
    for (int idx = threadIdx.x; idx < 16 * 32; idx += blockDim.x) {
        int li = idx & 31;
        int t = idx >> 5;
        int nt = (t >> 2) + 8, kt = t & 3;
        int gi = li >> 2, mi = li & 3;
        unsigned h0, l0, h1, l1;
        tf32_split(__ldg(&Up[(kt * 8 + mi)     * 96 + nt * 8 + gi]), h0, l0);
        tf32_split(__ldg(&Up[(kt * 8 + mi + 4) * 96 + nt * 8 + gi]), h1, l1);
        sBn[idx] = make_uint4(h0, h1, l0, l1);
    }
    __syncthreads();

    int wid = (blockIdx.x * blockDim.x + threadIdx.x) >> 5;
    int p0 = wid * 16;
    if (p0 >= PN) return;
    int g = lane >> 2, m = lane & 3;
    int pA = p0 + g, pB = p0 + g + 8;

    float h[4][4];
#pragma unroll
    for (int jt = 0; jt < 4; jt++) {
        float2 ha = *(const float2*)&g_path_state[pA * DD + 8 * jt + 2 * m];
        float2 hb = *(const float2*)&g_path_state[pB * DD + 8 * jt + 2 * m];
        h[jt][0] = ha.x; h[jt][1] = ha.y; h[jt][2] = hb.x; h[jt][3] = hb.y;
    }

    int src0 = (lane & ~3) | (m >> 1);
    int src1 = src0 + 2;
    bool odd = (m & 1);

#pragma unroll 1
    for (int s = 0; s < LLEN; s++) {
        int lkA = __ldg(&links[pA * LLEN + s]);
        int lkB = __ldg(&links[pB * LLEN + s]);
        const float* lgA = g_lg + (size_t)lkA * 96;
        const float* lgB = g_lg + (size_t)lkB * 96;

        float2 xg[2][3][4];   // [path][gate][jt] — issued early, consumed post-mma
#pragma unroll
        for (int gate = 0; gate < 3; gate++)
#pragma unroll
            for (int jt = 0; jt < 4; jt++) {
                xg[0][gate][jt] = *(const float2*)&lgA[gate * 32 + 8 * jt + 2 * m];
                xg[1][gate][jt] = *(const float2*)&lgB[gate * 32 + 8 * jt + 2 * m];
            }

        float d[12][4];
#pragma unroll
        for (int nt = 0; nt < 8; nt++) {            // z/r: biases folded into lg
            d[nt][0] = 0.0f; d[nt][1] = 0.0f; d[nt][2] = 0.0f; d[nt][3] = 0.0f;
        }
#pragma unroll
        for (int nt = 8; nt < 12; nt++) {           // n: recurrent bias load (L1-hit)
            int jt = nt & 3;
            float2 br = *(const float2*)&bp[160 + 8 * jt + 2 * m];
            d[nt][0] = br.x; d[nt][1] = br.y; d[nt][2] = br.x; d[nt][3] = br.y;
        }

#pragma unroll
        for (int kt = 0; kt < 4; kt++) {
            float v[4];
            float s00 = __shfl_sync(0xffffffffu, h[kt][0], src0);
            float s01 = __shfl_sync(0xffffffffu, h[kt][1], src0);
            v[0] = odd ? s01 : s00;
            float s10 = __shfl_sync(0xffffffffu, h[kt][2], src0);
            float s11 = __shfl_sync(0xffffffffu, h[kt][3], src0);
            v[1] = odd ? s11 : s10;
            float s20 = __shfl_sync(0xffffffffu, h[kt][0], src1);
            float s21 = __shfl_sync(0xffffffffu, h[kt][1], src1);
            v[2] = odd ? s21 : s20;
            float s30 = __shfl_sync(0xffffffffu, h[kt][2], src1);
            float s31 = __shfl_sync(0xffffffffu, h[kt][3], src1);
            v[3] = odd ? s31 : s30;
            unsigned ah[4], al[4];
#pragma unroll
            for (int e = 0; e < 4; e++) tf32_split(v[e], ah[e], al[e]);
#pragma unroll
            for (int nt = 0; nt < 8; nt++)
                mma2h(d[nt], ah, al, sBzr[(nt * 4 + kt) * 32 + lane]);
#pragma unroll
            for (int nt = 8; nt < 12; nt++)
                mma3(d[nt], ah, al, sBn[((nt - 8) * 4 + kt) * 32 + lane]);
        }

#pragma unroll
        for (int jt = 0; jt < 4; jt++) {
            float xz[4] = {xg[0][0][jt].x, xg[0][0][jt].y, xg[1][0][jt].x, xg[1][0][jt].y};
            float xr[4] = {xg[0][1][jt].x, xg[0][1][jt].y, xg[1][1][jt].x, xg[1][1][jt].y};
            float xn[4] = {xg[0][2][jt].x, xg[0][2][jt].y, xg[1][2][jt].x, xg[1][2][jt].y};
#pragma unroll
            for (int e = 0; e < 4; e++) {
                float z = fsig(d[jt][e] + xz[e]);
                float r = fsig(d[4 + jt][e] + xr[e]);
                float n = ftanhf_(fmaf(r, d[8 + jt][e], xn[e]));
                h[jt][e] = fmaf(z, h[jt][e] - n, n);
            }
            if (do_scatter) {
                int cA = 8 * jt + 2 * m;
                atomicAdd((float2*)&g_m[lkA * DD + cA], make_float2(h[jt][0], h[jt][1]));
                atomicAdd((float2*)&g_m[lkB * DD + cA], make_float2(h[jt][2], h[jt][3]));
            }
        }
    }

#pragma unroll
    for (int jt = 0; jt < 4; jt++) {
        *(float2*)&g_path_state[pA * DD + 8 * jt + 2 * m] = make_float2(h[jt][0], h[jt][1]);
        *(float2*)&g_path_state[pB * DD + 8 * jt + 2 * m] = make_float2(h[jt][2], h[jt][3]);
    }
}

// ---------------------------------------------------------------------------
// Link phase via tensor cores (3xTF32). lg epilogue now folds recurrent z/r
// bias (bp[96+col]) for z/r columns, matching init_all_kernel.
__global__ void __launch_bounds__(128)
link_mma_kernel(const float* __restrict__ Wl, const float* __restrict__ Ul,
                const float* __restrict__ bl,
                const float* __restrict__ Wp, const float* __restrict__ bp) {
    __shared__ float2 sWl[48 * 32], sUl[48 * 32], sWp[48 * 32];   // 36KB

    int lane = threadIdx.x & 31;
    for (int idx = threadIdx.x; idx < 48 * 32; idx += blockDim.x) {
        int li = idx & 31;
        int t = idx >> 5;
        int nt = t >> 2, kt = t & 3;
        int gi = li >> 2, mi = li & 3;
        int r0 = (kt * 8 + mi) * 96 + nt * 8 + gi;
        int r1 = (kt * 8 + mi + 4) * 96 + nt * 8 + gi;
        sWl[idx] = make_float2(__ldg(&Wl[r0]), __ldg(&Wl[r1]));
        sUl[idx] = make_float2(__ldg(&Ul[r0]), __ldg(&Ul[r1]));
        sWp[idx] = make_float2(__ldg(&Wp[r0]), __ldg(&Wp[r1]));
    }
    __syncthreads();

    int wid = (blockIdx.x * blockDim.x + threadIdx.x) >> 5;
    int l0 = wid * 16;
    if (l0 >= NLK) return;
    int g = lane >> 2, m = lane & 3;
    int lA = l0 + g, lB = l0 + g + 8;

    unsigned xh[4][4], xlo[4][4], hh[4][4], hlo[4][4];
#pragma unroll
    for (int kt = 0; kt < 4; kt++) {
        tf32_split(g_m[lA * DD + kt * 8 + m],     xh[kt][0], xlo[kt][0]);
        tf32_split(g_m[lB * DD + kt * 8 + m],     xh[kt][1], xlo[kt][1]);
        tf32_split(g_m[lA * DD + kt * 8 + m + 4], xh[kt][2], xlo[kt][2]);
        tf32_split(g_m[lB * DD + kt * 8 + m + 4], xh[kt][3], xlo[kt][3]);
        tf32_split(g_link_state[lA * DD + kt * 8 + m],     hh[kt][0], hlo[kt][0]);
        tf32_split(g_link_state[lB * DD + kt * 8 + m],     hh[kt][1], hlo[kt][1]);
        tf32_split(g_link_state[lA * DD + kt * 8 + m + 4], hh[kt][2], hlo[kt][2]);
        tf32_split(g_link_state[lB * DD + kt * 8 + m + 4], hh[kt][3], hlo[kt][3]);
    }

    float dz[4][4], dr[4][4], dxn[4][4], dhn[4][4];
#pragma unroll
    for (int jt = 0; jt < 4; jt++) {
        int col = 8 * jt + 2 * m;
        float2 b0z = *(const float2*)&bl[col];
        float2 b1z = *(const float2*)&bl[96 + col];
        dz[jt][0] = b0z.x + b1z.x; dz[jt][1] = b0z.y + b1z.y;
        dz[jt][2] = dz[jt][0];     dz[jt][3] = dz[jt][1];
        float2 b0r = *(const float2*)&bl[32 + col];
        float2 b1r = *(const float2*)&bl[128 + col];
        dr[jt][0] = b0r.x + b1r.x; dr[jt][1] = b0r.y + b1r.y;
        dr[jt][2] = dr[jt][0];     dr[jt][3] = dr[jt][1];
        float2 b0n = *(const float2*)&bl[64 + col];
        dxn[jt][0] = b0n.x; dxn[jt][1] = b0n.y; dxn[jt][2] = b0n.x; dxn[jt][3] = b0n.y;
        float2 b1n = *(const float2*)&bl[160 + col];
        dhn[jt][0] = b1n.x; dhn[jt][1] = b1n.y; dhn[jt][2] = b1n.x; dhn[jt][3] = b1n.y;
    }

#pragma unroll
    for (int jt = 0; jt < 4; jt++)
#pragma unroll
        for (int kt = 0; kt < 4; kt++) {
            float2 bw; unsigned bh0, bl0, bh1, bl1;
            bw = sWl[(jt * 4 + kt) * 32 + lane];
            tf32_split(bw.x, bh0, bl0); tf32_split(bw.y, bh1, bl1);
            mma_tf32(dz[jt], xh[kt], bh0, bh1);
            mma_tf32(dz[jt], xlo[kt], bh0, bh1);
            mma_tf32(dz[jt], xh[kt], bl0, bl1);
            bw = sUl[(jt * 4 + kt) * 32 + lane];
            tf32_split(bw.x, bh0, bl0); tf32_split(bw.y, bh1, bl1);
            mma_tf32(dz[jt], hh[kt], bh0, bh1);
            mma_tf32(dz[jt], hlo[kt], bh0, bh1);
            mma_tf32(dz[jt], hh[kt], bl0, bl1);
            bw = sWl[((4 + jt) * 4 + kt) * 32 + lane];
            tf32_split(bw.x, bh0, bl0); tf32_split(bw.y, bh1, bl1);
            mma_tf32(dr[jt], xh[kt], bh0, bh1);
            mma_tf32(dr[jt], xlo[kt], bh0, bh1);
            mma_tf32(dr[jt], xh[kt], bl0, bl1);
            bw = sUl[((4 + jt) * 4 + kt) * 32 + lane];
            tf32_split(bw.x, bh0, bl0); tf32_split(bw.y, bh1, bl1);
            mma_tf32(dr[jt], hh[kt], bh0, bh1);
            mma_tf32(dr[jt], hlo[kt], bh0, bh1);
            mma_tf32(dr[jt], hh[kt], bl0, bl1);
            bw = sWl[((8 + jt) * 4 + kt) * 32 + lane];
            tf32_split(bw.x, bh0, bl0); tf32_split(bw.y, bh1, bl1);
            mma_tf32(dxn[jt], xh[kt], bh0, bh1);
            mma_tf32(dxn[jt], xlo[kt], bh0, bh1);
            mma_tf32(dxn[jt], xh[kt], bl0, bl1);
            bw = sUl[((8 + jt) * 4 + kt) * 32 + lane];
            tf32_split(bw.x, bh0, bl0); tf32_split(bw.y, bh1, bl1);
            mma_tf32(dhn[jt], hh[kt], bh0, bh1);
            mma_tf32(dhn[jt], hlo[kt], bh0, bh1);
            mma_tf32(dhn[jt], hh[kt], bl0, bl1);
        }

    float h2[4][4];
#pragma unroll
    for (int jt = 0; jt < 4; jt++) {
        int col = 8 * jt + 2 * m;
        float2 hA = *(const float2*)&g_link_state[lA * DD + col];
        float2 hB = *(const float2*)&g_link_state[lB * DD + col];
        float hd[4] = {hA.x, hA.y, hB.x, hB.y};
#pragma unroll
        for (int e = 0; e < 4; e++) {
            float z = fsig(dz[jt][e]);
            float r = fsig(dr[jt][e]);
            float n = ftanhf_(fmaf(r, dhn[jt][e], dxn[jt][e]));
            h2[jt][e] = fmaf(z, hd[e] - n, n);
        }
        *(float2*)&g_link_state[lA * DD + col] = make_float2(h2[jt][0], h2[jt][1]);
        *(float2*)&g_link_state[lB * DD + col] = make_float2(h2[jt][2], h2[jt][3]);
        *(float2*)&g_m[lA * DD + col] = make_float2(0.0f, 0.0f);
        *(float2*)&g_m[lB * DD + col] = make_float2(0.0f, 0.0f);
    }

    int src0 = (lane & ~3) | (m >> 1);
    int src1 = src0 + 2;
    bool odd = (m & 1);
    unsigned ah[4][4], al[4][4];
#pragma unroll
    for (int kt = 0; kt < 4; kt++) {
        float v[4];
        float s00 = __shfl_sync(0xffffffffu, h2[kt][0], src0);
        float s01 = __shfl_sync(0xffffffffu, h2[kt][1], src0);
        v[0] = odd ? s01 : s00;
        float s10 = __shfl_sync(0xffffffffu, h2[kt][2], src0);
        float s11 = __shfl_sync(0xffffffffu, h2[kt][3], src0);
        v[1] = odd ? s11 : s10;
        float s20 = __shfl_sync(0xffffffffu, h2[kt][0], src1);
        float s21 = __shfl_sync(0xffffffffu, h2[kt][1], src1);
        v[2] = odd ? s21 : s20;
        float s30 = __shfl_sync(0xffffffffu, h2[kt][2], src1);
        float s31 = __shfl_sync(0xffffffffu, h2[kt][3], src1);
        v[3] = odd ? s31 : s30;
#pragma unroll
        for (int e = 0; e < 4; e++) tf32_split(v[e], ah[kt][e], al[kt][e]);
    }
#pragma unroll
    for (int nt = 0; nt < 12; nt++) {
        float d2[4];
        int col = nt * 8 + 2 * m;
        float2 b = *(const float2*)&bp[col];
        if (nt < 8) {                       // fold recurrent z/r bias into lg
            float2 b1 = *(const float2*)&bp[96 + col];
            b.x += b1.x; b.y += b1.y;
        }
        d2[0] = b.x; d2[1] = b.y; d2[2] = b.x; d2[3] = b.y;
#pragma unroll
        for (int kt = 0; kt < 4; kt++) {
            float2 bw = sWp[(nt * 4 + kt) * 32 + lane];
            unsigned bh0, bl0, bh1, bl1;
            tf32_split(bw.x, bh0, bl0); tf32_split(bw.y, bh1, bl1);
            mma_tf32(d2, ah[kt], bh0, bh1);
            mma_tf32(d2, al[kt], bh0, bh1);
            mma_tf32(d2, ah[kt], bl0, bl1);
        }
        *(float2*)&g_lg[lA * 96 + col] = make_float2(d2[0], d2[1]);
        *(float2*)&g_lg[lB * 96 + col] = make_float2(d2[2], d2[3]);
    }
}

// ---------------------------------------------------------------------------
// Readout layer 1: H1 = selu(PS @ R1 + b1), stored fp16.
__global__ void __launch_bounds__(256)
readout1_kernel(const float* __restrict__ R1, const float* __restrict__ Rb1) {
    __shared__ float2 sB[32 * 4 * 32];

    int lane = threadIdx.x & 31;
    for (int idx = threadIdx.x; idx < 32 * 4 * 32; idx += blockDim.x) {
        int li = idx & 31;
        int t = idx >> 5;
        int nt = t >> 2, kt = t & 3;
        int gi = li >> 2, mi = li & 3;
        sB[idx] = make_float2(__ldg(&R1[(kt * 8 + mi)     * RUN + nt * 8 + gi]),
                              __ldg(&R1[(kt * 8 + mi + 4) * RUN + nt * 8 + gi]));
    }
    __syncthreads();

    int wid = (blockIdx.x * blockDim.x + threadIdx.x) >> 5;
    int p0 = wid * 16;
    if (p0 >= PN) return;
    int g = lane >> 2, m = lane & 3;
    int pA = p0 + g, pB = p0 + g + 8;

    unsigned ah[4][4], al[4][4];
#pragma unroll
    for (int kt = 0; kt < 4; kt++) {
        tf32_split(__ldg(&g_path_state[pA * DD + kt * 8 + m]),     ah[kt][0], al[kt][0]);
        tf32_split(__ldg(&g_path_state[pB * DD + kt * 8 + m]),     ah[kt][1], al[kt][1]);
        tf32_split(__ldg(&g_path_state[pA * DD + kt * 8 + m + 4]), ah[kt][2], al[kt][2]);
        tf32_split(__ldg(&g_path_state[pB * DD + kt * 8 + m + 4]), ah[kt][3], al[kt][3]);
    }

#pragma unroll 1
    for (int half = 0; half < 2; half++) {
        float d[16][4];
#pragma unroll
        for (int ntl = 0; ntl < 16; ntl++) {
            int col = (half * 16 + ntl) * 8 + 2 * m;
            float2 b = *(const float2*)&Rb1[col];
            d[ntl][0] = b.x; d[ntl][1] = b.y; d[ntl][2] = b.x; d[ntl][3] = b.y;
        }
#pragma unroll
        for (int ntl = 0; ntl < 16; ntl++) {
            int nt = half * 16 + ntl;
#pragma unroll
            for (int kt = 0; kt < 4; kt++) {
                float2 b = sB[(nt * 4 + kt) * 32 + lane];
                unsigned bh0, bl0, bh1, bl1;
                tf32_split(b.x, bh0, bl0);
                tf32_split(b.y, bh1, bl1);
                mma_tf32(d[ntl], ah[kt], bh0, bh1);
                mma_tf32(d[ntl], al[kt], bh0, bh1);
                mma_tf32(d[ntl], ah[kt], bl0, bl1);
            }
        }
#pragma unroll
        for (int ntl = 0; ntl < 16; ntl++) {
            int col = (half * 16 + ntl) * 8 + 2 * m;
            *(__half2*)&g_h1[pA * RUN + col] =
                __floats2half2_rn(fselu(d[ntl][0]), fselu(d[ntl][1]));
            *(__half2*)&g_h1[pB * RUN + col] =
                __floats2half2_rn(fselu(d[ntl][2]), fselu(d[ntl][3]));
        }
    }
}

// ---------------------------------------------------------------------------
// Readout layers 2+3: out = selu(H1 @ R2 + b2) @ R3 + b3. A fp16-exact in tf32.
__global__ void __launch_bounds__(256)
readout2_kernel(const float* __restrict__ R2, const float* __restrict__ Rb2,
                const float* __restrict__ R3, const float* __restrict__ Rb3,
                float* __restrict__ out) {
    __shared__ float2 sB[16 * 8 * 32];

    int lane = threadIdx.x & 31;
    int wid = (blockIdx.x * blockDim.x + threadIdx.x) >> 5;
    int p0 = wid * 16;
    bool active = (p0 < PN);
    int g = lane >> 2, m = lane & 3;
    int pA = p0 + g, pB = p0 + g + 8;

    float accA = 0.0f, accB = 0.0f;

#pragma unroll 1
    for (int half = 0; half < 2; half++) {
        float d[16][4];
        if (active) {
#pragma unroll
            for (int ntl = 0; ntl < 16; ntl++) {
                int col = half * 128 + ntl * 8 + 2 * m;
                float2 b = *(const float2*)&Rb2[col];
                d[ntl][0] = b.x; d[ntl][1] = b.y; d[ntl][2] = b.x; d[ntl][3] = b.y;
            }
        }
#pragma unroll 1
        for (int kc = 0; kc < 4; kc++) {
            __syncthreads();
            for (int idx = threadIdx.x; idx < 16 * 8 * 32; idx += blockDim.x) {
                int li = idx & 31;
                int t = idx >> 5;
                int ntl = t >> 3, kt = t & 7;
                int gi = li >> 2, mi = li & 3;
                int krow = kc * 64 + kt * 8;
                int col = half * 128 + ntl * 8 + gi;
                sB[idx] = make_float2(__ldg(&R2[(krow + mi)     * RUN + col]),
                                      __ldg(&R2[(krow + mi + 4) * RUN + col]));
            }
            __syncthreads();
            if (!active) continue;

            unsigned a[8][4];
#pragma unroll
            for (int kt = 0; kt < 8; kt++) {
                int k0 = kc * 64 + kt * 8;
                a[kt][0] = cvt_tf32(__half2float(g_h1[pA * RUN + k0 + m]));
                a[kt][1] = cvt_tf32(__half2float(g_h1[pB * RUN + k0 + m]));
                a[kt][2] = cvt_tf32(__half2float(g_h1[pA * RUN + k0 + m + 4]));
                a[kt][3] = cvt_tf32(__half2float(g_h1[pB * RUN + k0 + m + 4]));
            }
#pragma unroll
            for (int ntl = 0; ntl < 16; ntl++)
#pragma unroll
                for (int kt = 0; kt < 8; kt++) {
                    float2 b = sB[(ntl * 8 + kt) * 32 + lane];
                    unsigned bh0, bl0, bh1, bl1;
                    tf32_split(b.x, bh0, bl0);
                    tf32_split(b.y, bh1, bl1);
                    mma_tf32(d[ntl], a[kt], bh0, bh1);
                    mma_tf32(d[ntl], a[kt], bl0, bl1);
                }
        }
        if (active) {
#pragma unroll
            for (int ntl = 0; ntl < 16; ntl++) {
                int col = half * 128 + ntl * 8 + 2 * m;
                float2 r3 = *(const float2*)&R3[col];
                accA = fmaf(fselu(d[ntl][0]), r3.x, accA);
                accA = fmaf(fselu(d[ntl][1]), r3.y, accA);
                accB = fmaf(fselu(d[ntl][2]), r3.x, accB);
                accB = fmaf(fselu(d[ntl][3]), r3.y, accB);
            }
        }
    }

    if (active) {
        accA += __shfl_xor_sync(0xffffffffu, accA, 1);
        accA += __shfl_xor_sync(0xffffffffu, accA, 2);
        accB += __shfl_xor_sync(0xffffffffu, accB, 1);
        accB += __shfl_xor_sync(0xffffffffu, accB, 2);
        if (m == 0) {
            float b3 = __ldg(&Rb3[0]);
            out[pA] = accA + b3;
            out[pB] = accB + b3;
        }
    }
}

// ---------------------------------------------------------------------------
extern "C" void kernel_launch(void* const* d_in, const int* in_sizes, int n_in,
                              void* d_out, int out_size) {
    const int*   links = (const int*)d_in[0];
    const float* cap = (const float*)d_in[3];
    const float* pol = (const float*)d_in[4];
    const float* wt  = (const float*)d_in[5];
    const float* bw  = (const float*)d_in[6];
    const float* tos = (const float*)d_in[7];
    const float* pk  = (const float*)d_in[8];
    const float* avg = (const float*)d_in[9];
    const float* Wp  = (const float*)d_in[10];
    const float* Up  = (const float*)d_in[11];
    const float* bp  = (const float*)d_in[12];
    const float* Wl  = (const float*)d_in[13];
    const float* Ul  = (const float*)d_in[14];
    const float* bl  = (const float*)d_in[15];
    const float* R1  = (const float*)d_in[16];
    const float* Rb1 = (const float*)d_in[17];
    const float* R2  = (const float*)d_in[18];
    const float* Rb2 = (const float*)d_in[19];
    const float* R3  = (const float*)d_in[20];
    const float* Rb3 = (const float*)d_in[21];
    float* out = (float*)d_out;

    init_all_kernel<<<(PN * DD + 255) / 256, 256>>>(bw, tos, pk, avg, cap, pol, wt, Wp, bp);

    int nwarps = (PN + 15) / 16;               // 6250
    int pblocks = (nwarps + 3) / 4;            // 128 threads = 4 warps per block
    int lwarps = (NLK + 15) / 16;              // 625
    int lblocks = (lwarps + 3) / 4;            // 157
    for (int t = 0; t < TT; t++) {
        path_mma_kernel<<<pblocks, 128>>>(links, Up, bp, t < TT - 1 ? 1 : 0);
        if (t < TT - 1)
            link_mma_kernel<<<lblocks, 128>>>(Wl, Ul, bl, Wp, bp);
    }

    int rblocks = (nwarps + 7) / 8;            // 256 threads = 8 warps per block
    readout1_kernel<<<rblocks, 256>>>(R1, Rb1);
    readout2_kernel<<<rblocks, 256>>>(R2, Rb2, R3, Rb3, out);
}